// round 1
// baseline (speedup 1.0000x reference)
#include <cuda_runtime.h>
#include <cstdint>
#include <cstddef>

// ---------------- problem dims ----------------
#define NN 50000
#define FF 256
#define EE 200000
#define HH 4
#define CC 128
#define GG 256
#define NCLS 10
#define HC 512            // H*C
#define EPS 1e-16f

// ---------------- scratch (device globals; no allocations allowed) ----------
__device__ float    g_q[(size_t)NN * HC];
__device__ float    g_k[(size_t)NN * HC];
__device__ float    g_v[(size_t)NN * HC];
__device__ float    g_h1[(size_t)NN * HC];    // layer1 output (skip + msg, then elu)
__device__ float    g_h2[(size_t)NN * CC];    // layer2 output
__device__ float    g_alpha[(size_t)EE * HH]; // per-edge scores -> exp values
__device__ unsigned g_m[(size_t)NN * HH];     // encoded segment max
__device__ float    g_s[(size_t)NN * HH];     // segment sum of exp
__device__ float    g_pool[(size_t)GG * CC];
__device__ float    g_cnt[GG];

// monotone float<->uint encoding for atomicMax on floats (handles negatives)
__device__ __forceinline__ unsigned fenc(float f) {
    unsigned u = __float_as_uint(f);
    return (u & 0x80000000u) ? ~u : (u | 0x80000000u);
}
__device__ __forceinline__ float fdec(unsigned e) {
    return (e & 0x80000000u) ? __uint_as_float(e ^ 0x80000000u)
                             : __uint_as_float(~e);
}

// ---------------- SGEMM: C[n,M] = A[n,K] @ B[K,M] + bias ----------------
// BM=BN=128, BK=16, 256 threads, 8x8 per thread. K % 16 == 0, M % 128 == 0.
__global__ __launch_bounds__(256) void sgemm_bias(
    const float* __restrict__ A, const float* __restrict__ B,
    const float* __restrict__ bias, float* __restrict__ Cmat,
    int nrows, int K, int M)
{
    __shared__ float As[16][128];
    __shared__ float Bs[16][128];
    const int tid = threadIdx.x;
    const int tx = tid & 15;          // 0..15 -> N dim
    const int ty = tid >> 4;          // 0..15 -> M(row) dim
    const int rowBase = blockIdx.y * 128;
    const int colBase = blockIdx.x * 128;

    float acc[8][8];
#pragma unroll
    for (int i = 0; i < 8; i++)
#pragma unroll
        for (int j = 0; j < 8; j++) acc[i][j] = 0.f;

    for (int k0 = 0; k0 < K; k0 += 16) {
        // A tile: 128 rows x 16 cols -> store transposed As[k][row]
#pragma unroll
        for (int i = 0; i < 2; i++) {
            int lin = tid + i * 256;        // 0..511 float4 slots
            int ar = lin >> 2;              // tile row 0..127
            int ac = (lin & 3) * 4;         // tile col 0,4,8,12
            int grow = rowBase + ar;
            float4 val = make_float4(0.f, 0.f, 0.f, 0.f);
            if (grow < nrows)
                val = *reinterpret_cast<const float4*>(&A[(size_t)grow * K + k0 + ac]);
            As[ac + 0][ar] = val.x;
            As[ac + 1][ar] = val.y;
            As[ac + 2][ar] = val.z;
            As[ac + 3][ar] = val.w;
        }
        // B tile: 16 rows x 128 cols
#pragma unroll
        for (int i = 0; i < 2; i++) {
            int lin = tid + i * 256;
            int br = lin >> 5;              // 0..15
            int bc = (lin & 31) * 4;        // 0..124
            float4 val = *reinterpret_cast<const float4*>(
                &B[(size_t)(k0 + br) * M + colBase + bc]);
            *reinterpret_cast<float4*>(&Bs[br][bc]) = val;
        }
        __syncthreads();

#pragma unroll
        for (int kk = 0; kk < 16; kk++) {
            float ra[8], rb[8];
#pragma unroll
            for (int i = 0; i < 8; i++) ra[i] = As[kk][ty * 8 + i];
#pragma unroll
            for (int j = 0; j < 8; j++) rb[j] = Bs[kk][tx * 8 + j];
#pragma unroll
            for (int i = 0; i < 8; i++)
#pragma unroll
                for (int j = 0; j < 8; j++) acc[i][j] += ra[i] * rb[j];
        }
        __syncthreads();
    }

    // epilogue: bias + store
#pragma unroll
    for (int i = 0; i < 8; i++) {
        int grow = rowBase + ty * 8 + i;
        if (grow >= nrows) break;
#pragma unroll
        for (int j = 0; j < 8; j += 4) {
            int gcol = colBase + tx * 8 + j;
            float4 o;
            o.x = acc[i][j + 0] + bias[gcol + 0];
            o.y = acc[i][j + 1] + bias[gcol + 1];
            o.z = acc[i][j + 2] + bias[gcol + 2];
            o.w = acc[i][j + 3] + bias[gcol + 3];
            *reinterpret_cast<float4*>(&Cmat[(size_t)grow * M + gcol]) = o;
        }
    }
}

// ---------------- attention kernels ----------------
__global__ void init_ms(unsigned* __restrict__ m, float* __restrict__ s, int n) {
    int i = blockIdx.x * blockDim.x + threadIdx.x;
    if (i < n) { m[i] = 0x007FFFFFu; s[i] = 0.f; }   // fenc(-inf)
}

// one block per edge, one warp per head: alpha = q[dst,h]·k[src,h] / sqrt(C)
__global__ __launch_bounds__(128) void edge_alpha(
    const float* __restrict__ q, const float* __restrict__ k,
    const int* __restrict__ ei, float* __restrict__ alpha,
    unsigned* __restrict__ mmax)
{
    int e = blockIdx.x;
    int w = threadIdx.x >> 5;
    int lane = threadIdx.x & 31;
    int src = ei[e];
    int dst = ei[EE + e];
    float4 a4 = reinterpret_cast<const float4*>(q + (size_t)dst * HC + w * CC)[lane];
    float4 b4 = reinterpret_cast<const float4*>(k + (size_t)src * HC + w * CC)[lane];
    float s = a4.x * b4.x + a4.y * b4.y + a4.z * b4.z + a4.w * b4.w;
#pragma unroll
    for (int off = 16; off; off >>= 1) s += __shfl_xor_sync(0xFFFFFFFFu, s, off);
    if (lane == 0) {
        s *= 0.08838834764831845f;  // 1/sqrt(128)
        alpha[(size_t)e * HH + w] = s;
        atomicMax(&mmax[(size_t)dst * HH + w], fenc(s));
    }
}

__global__ void edge_expsum(const int* __restrict__ ei, float* __restrict__ alpha,
                            const unsigned* __restrict__ mmax, float* __restrict__ ssum)
{
    int i = blockIdx.x * blockDim.x + threadIdx.x;
    if (i >= EE * HH) return;
    int e = i >> 2;
    int h = i & 3;
    int dst = ei[EE + e];
    float m = fdec(mmax[(size_t)dst * HH + h]);
    float ex = expf(alpha[i] - m);
    alpha[i] = ex;
    atomicAdd(&ssum[(size_t)dst * HH + h], ex);
}

// one block per edge, one warp per head: out[dst] += a * v[src]
__global__ __launch_bounds__(128) void edge_scatter(
    const float* __restrict__ v, const int* __restrict__ ei,
    const float* __restrict__ alpha, const float* __restrict__ ssum,
    float* __restrict__ out, int concat)
{
    int e = blockIdx.x;
    int w = threadIdx.x >> 5;
    int lane = threadIdx.x & 31;
    int src = ei[e];
    int dst = ei[EE + e];
    float a = alpha[(size_t)e * HH + w] / (ssum[(size_t)dst * HH + w] + EPS);
    float4 vv = reinterpret_cast<const float4*>(v + (size_t)src * HC + w * CC)[lane];
    float* o;
    if (concat) {
        o = out + (size_t)dst * HC + w * CC + lane * 4;
    } else {
        a *= 0.25f;  // mean over H=4 heads
        o = out + (size_t)dst * CC + lane * 4;
    }
    atomicAdd(o + 0, a * vv.x);
    atomicAdd(o + 1, a * vv.y);
    atomicAdd(o + 2, a * vv.z);
    atomicAdd(o + 3, a * vv.w);
}

__global__ void elu_k(float* __restrict__ x, size_t n) {
    size_t i = (size_t)blockIdx.x * blockDim.x + threadIdx.x;
    if (i < n) {
        float v = x[i];
        x[i] = v > 0.f ? v : expm1f(v);
    }
}

// ---------------- pooling + head ----------------
__global__ void zero_pool(float* __restrict__ pool, float* __restrict__ cnt) {
    int i = blockIdx.x * blockDim.x + threadIdx.x;
    if (i < GG * CC) pool[i] = 0.f;
    if (i < GG) cnt[i] = 0.f;
}

__global__ __launch_bounds__(128) void pool_k(
    const float* __restrict__ h, const int* __restrict__ batch,
    float* __restrict__ pool, float* __restrict__ cnt)
{
    int i = blockIdx.x;   // node
    int g = batch[i];
    int c = threadIdx.x;  // channel
    atomicAdd(&pool[(size_t)g * CC + c], h[(size_t)i * CC + c]);
    if (c == 0) atomicAdd(&cnt[g], 1.f);
}

__global__ __launch_bounds__(128) void head_k(
    const float* __restrict__ pool, const float* __restrict__ cnt,
    const float* __restrict__ Wfc, const float* __restrict__ bfc,
    float* __restrict__ out)
{
    int g = blockIdx.x;
    int t = threadIdx.x;
    __shared__ float sm[CC];
    __shared__ float logits[NCLS];
    float cv = fmaxf(cnt[g], 1.f);
    sm[t] = pool[(size_t)g * CC + t] / cv;
    __syncthreads();
    if (t < NCLS) {
        float acc = bfc[t];
#pragma unroll 4
        for (int c = 0; c < CC; c++) acc += sm[c] * Wfc[c * NCLS + t];
        logits[t] = acc;
    }
    __syncthreads();
    if (t == 0) {
        float mx = -1e30f;
#pragma unroll
        for (int j = 0; j < NCLS; j++) mx = fmaxf(mx, logits[j]);
        float ssum = 0.f;
#pragma unroll
        for (int j = 0; j < NCLS; j++) ssum += expf(logits[j] - mx);
        float lse = mx + logf(ssum);
#pragma unroll
        for (int j = 0; j < NCLS; j++) out[g * NCLS + j] = logits[j] - lse;
    }
}

// ---------------- launch ----------------
extern "C" void kernel_launch(void* const* d_in, const int* in_sizes, int n_in,
                              void* d_out, int out_size)
{
    const float* x     = (const float*)d_in[0];
    const int*   ei    = (const int*)d_in[1];
    const int*   batch = (const int*)d_in[2];
    const float* Wq1 = (const float*)d_in[3];  const float* bq1 = (const float*)d_in[4];
    const float* Wk1 = (const float*)d_in[5];  const float* bk1 = (const float*)d_in[6];
    const float* Wv1 = (const float*)d_in[7];  const float* bv1 = (const float*)d_in[8];
    const float* Ws1 = (const float*)d_in[9];  const float* bs1 = (const float*)d_in[10];
    const float* Wq2 = (const float*)d_in[11]; const float* bq2 = (const float*)d_in[12];
    const float* Wk2 = (const float*)d_in[13]; const float* bk2 = (const float*)d_in[14];
    const float* Wv2 = (const float*)d_in[15]; const float* bv2 = (const float*)d_in[16];
    const float* Ws2 = (const float*)d_in[17]; const float* bs2 = (const float*)d_in[18];
    const float* Wfc = (const float*)d_in[19]; const float* bfc = (const float*)d_in[20];
    float* out = (float*)d_out;

    float *q, *k, *v, *h1, *h2, *alpha, *s, *pool, *cnt;
    unsigned* m;
    cudaGetSymbolAddress((void**)&q, g_q);
    cudaGetSymbolAddress((void**)&k, g_k);
    cudaGetSymbolAddress((void**)&v, g_v);
    cudaGetSymbolAddress((void**)&h1, g_h1);
    cudaGetSymbolAddress((void**)&h2, g_h2);
    cudaGetSymbolAddress((void**)&alpha, g_alpha);
    cudaGetSymbolAddress((void**)&m, g_m);
    cudaGetSymbolAddress((void**)&s, g_s);
    cudaGetSymbolAddress((void**)&pool, g_pool);
    cudaGetSymbolAddress((void**)&cnt, g_cnt);

    const int rowBlocks = (NN + 127) / 128;
    dim3 gemmGridWide(HC / 128, rowBlocks);  // M=512
    dim3 gemmGridNarrow(CC / 128, rowBlocks); // M=128

    // ---------- layer 1 (K = F = 256) ----------
    sgemm_bias<<<gemmGridWide, 256>>>(x, Wq1, bq1, q, NN, FF, HC);
    sgemm_bias<<<gemmGridWide, 256>>>(x, Wk1, bk1, k, NN, FF, HC);
    sgemm_bias<<<gemmGridWide, 256>>>(x, Wv1, bv1, v, NN, FF, HC);
    sgemm_bias<<<gemmGridWide, 256>>>(x, Ws1, bs1, h1, NN, FF, HC); // skip into h1

    init_ms<<<(NN * HH + 255) / 256, 256>>>(m, s, NN * HH);
    edge_alpha<<<EE, 128>>>(q, k, ei, alpha, m);
    edge_expsum<<<(EE * HH + 255) / 256, 256>>>(ei, alpha, m, s);
    edge_scatter<<<EE, 128>>>(v, ei, alpha, s, h1, 1);
    elu_k<<<(int)(((size_t)NN * HC + 255) / 256), 256>>>(h1, (size_t)NN * HC);

    // ---------- layer 2 (K = HC = 512) ----------
    sgemm_bias<<<gemmGridWide, 256>>>(h1, Wq2, bq2, q, NN, HC, HC);
    sgemm_bias<<<gemmGridWide, 256>>>(h1, Wk2, bk2, k, NN, HC, HC);
    sgemm_bias<<<gemmGridWide, 256>>>(h1, Wv2, bv2, v, NN, HC, HC);
    sgemm_bias<<<gemmGridNarrow, 256>>>(h1, Ws2, bs2, h2, NN, HC, CC); // skip into h2

    init_ms<<<(NN * HH + 255) / 256, 256>>>(m, s, NN * HH);
    edge_alpha<<<EE, 128>>>(q, k, ei, alpha, m);
    edge_expsum<<<(EE * HH + 255) / 256, 256>>>(ei, alpha, m, s);
    edge_scatter<<<EE, 128>>>(v, ei, alpha, s, h2, 0);
    elu_k<<<(int)(((size_t)NN * CC + 255) / 256), 256>>>(h2, (size_t)NN * CC);

    // ---------- pooling + classifier ----------
    zero_pool<<<(GG * CC + 255) / 256, 256>>>(pool, cnt);
    pool_k<<<NN, 128>>>(h2, batch, pool, cnt);
    head_k<<<GG, 128>>>(pool, cnt, Wfc, bfc, out);
}

// round 3
// speedup vs baseline: 1.8607x; 1.8607x over previous
#include <cuda_runtime.h>
#include <cuda_bf16.h>
#include <cstdint>
#include <cstddef>

// ---------------- problem dims ----------------
#define NN 50000
#define FF 256
#define EE 200000
#define HH 4
#define CC 128
#define GG 256
#define NCLS 10
#define EPS 1e-16f

#define N1 2048            // layer1 fused output cols: q|k|v|skip (4*512)
#define N2 1664            // layer2 fused output cols: q|k|v (3*512) | skip (128)
#define KMAX 512

// ---------------- scratch (device globals) ----------------
__device__ __align__(256) float         g_qkvs1[(size_t)NN * N1];
__device__ __align__(256) float         g_qkvs2[(size_t)NN * N2];
__device__ __align__(256) __nv_bfloat16 g_Ah[(size_t)NN * KMAX];
__device__ __align__(256) __nv_bfloat16 g_Al[(size_t)NN * KMAX];
__device__ __align__(256) __nv_bfloat16 g_Bh[(size_t)N1 * KMAX];
__device__ __align__(256) __nv_bfloat16 g_Bl[(size_t)N1 * KMAX];
__device__ __align__(256) float         g_biasv[N1];
__device__ __align__(256) float         g_alpha[(size_t)EE * HH];
__device__ __align__(256) unsigned      g_m[(size_t)NN * HH];
__device__ __align__(256) float         g_s[(size_t)NN * HH];
__device__ __align__(256) float         g_pool[GG * CC];
__device__ __align__(256) float         g_cnt[GG];

// ---------------- PTX helpers (all sm_80-compatible) ----------------
__device__ __forceinline__ uint32_t smem_u32(const void* p) {
    uint32_t a;
    asm("{ .reg .u64 t; cvta.to.shared.u64 t, %1; cvt.u32.u64 %0, t; }" : "=r"(a) : "l"(p));
    return a;
}
__device__ __forceinline__ void cp16(uint32_t dst, const void* src, unsigned srcsz) {
    asm volatile("cp.async.cg.shared.global [%0], [%1], 16, %2;"
                 :: "r"(dst), "l"(src), "r"(srcsz) : "memory");
}
__device__ __forceinline__ void ldsm4(uint32_t& r0, uint32_t& r1, uint32_t& r2, uint32_t& r3,
                                      uint32_t a) {
    asm volatile("ldmatrix.sync.aligned.m8n8.x4.shared.b16 {%0,%1,%2,%3}, [%4];"
                 : "=r"(r0), "=r"(r1), "=r"(r2), "=r"(r3) : "r"(a));
}
__device__ __forceinline__ void mma_bf16(float* c, const uint32_t* a, const uint32_t* b) {
    asm volatile(
        "mma.sync.aligned.m16n8k16.row.col.f32.bf16.bf16.f32 "
        "{%0,%1,%2,%3}, {%4,%5,%6,%7}, {%8,%9}, {%0,%1,%2,%3};"
        : "+f"(c[0]), "+f"(c[1]), "+f"(c[2]), "+f"(c[3])
        : "r"(a[0]), "r"(a[1]), "r"(a[2]), "r"(a[3]), "r"(b[0]), "r"(b[1]));
}

// ---------------- bf16x3 tensor-core GEMM ----------------
// C[row, col] = sum_k (Ah+Al)[row,k] * (Bh+Bl)[col,k] + bias[col]   (Al*Bl dropped)
// A tiles: [nrows, K] stride lda. B: [Ntot, KMAX] stride KMAX (pre-transposed).
// smem tile: 128 rows x 32 bf16, row stride 80B (pad -> conflict-free LDSM & STS).
#define TILE_B   (128 * 80)               // 10240 bytes per tile
#define STAGE_B  (4 * TILE_B)             // Ah,Al,Bh,Bl = 40960 bytes per stage
#define SMEM_GEMM (2 * STAGE_B)           // 81920 bytes

__global__ __launch_bounds__(256, 1)
void gemm_bf16x3(const __nv_bfloat16* __restrict__ Ahb, const __nv_bfloat16* __restrict__ Alb,
                 int lda, int K,
                 const __nv_bfloat16* __restrict__ Bhb, const __nv_bfloat16* __restrict__ Blb,
                 const float* __restrict__ bias, float* __restrict__ Cout, int ldo, int nrows)
{
    extern __shared__ char smem[];
    const uint32_t sb = smem_u32(smem);
    const int tid = threadIdx.x;
    const int lane = tid & 31;
    const int wid = tid >> 5;
    const int warpM = wid & 1;        // 2 m-halves of 64
    const int warpN = wid >> 1;       // 4 n-quarters of 32
    const int rowBase = blockIdx.y * 128;
    const int colBase = blockIdx.x * 128;

    float acc[4][4][4];               // [m16 tile][n8 tile][frag]
#pragma unroll
    for (int i = 0; i < 4; i++)
#pragma unroll
        for (int j = 0; j < 4; j++)
#pragma unroll
            for (int f = 0; f < 4; f++) acc[i][j][f] = 0.f;

    const int T = K >> 5;             // BK = 32

    auto loadStage = [&](int s, int k0) {
        uint32_t base = sb + s * STAGE_B;
#pragma unroll
        for (int t = 0; t < 2; t++) {
            int c = tid + t * 256;         // 0..511 chunks (16B) per tile
            int r = c >> 2;                // tile row 0..127
            int q = c & 3;                 // 16B chunk in row (8 bf16)
            uint32_t soff = (uint32_t)(r * 80 + q * 16);
            int ga = rowBase + r;
            unsigned va = (ga < nrows) ? 16u : 0u;
            int gac = (ga < nrows) ? ga : (nrows - 1);
            size_t aoff = (size_t)gac * lda + k0 + q * 8;
            cp16(base + soff,              Ahb + aoff, va);
            cp16(base + TILE_B + soff,     Alb + aoff, va);
            size_t boff = (size_t)(colBase + r) * KMAX + k0 + q * 8;
            cp16(base + 2 * TILE_B + soff, Bhb + boff, 16u);
            cp16(base + 3 * TILE_B + soff, Blb + boff, 16u);
        }
        asm volatile("cp.async.commit_group;" ::: "memory");
    };

    // per-thread ldmatrix address offsets (within a tile)
    const uint32_t aOff = (uint32_t)((warpM * 64 + (lane & 15)) * 80 + (lane >> 4) * 16);
    const uint32_t bOff = (uint32_t)((warpN * 32 + (lane & 7) + ((lane >> 4) & 1) * 8) * 80
                                     + ((lane >> 3) & 1) * 16);

    loadStage(0, 0);

    for (int it = 0; it < T; it++) {
        int s = it & 1;
        if (it + 1 < T) {
            loadStage(s ^ 1, (it + 1) << 5);
            asm volatile("cp.async.wait_group 1;" ::: "memory");
        } else {
            asm volatile("cp.async.wait_group 0;" ::: "memory");
        }
        __syncthreads();

        uint32_t tb = sb + s * STAGE_B;
#pragma unroll
        for (int ks = 0; ks < 2; ks++) {           // two k16 steps in BK=32
            uint32_t kb = ks * 32;
            uint32_t ah[4][4], al[4][4];
#pragma unroll
            for (int i = 0; i < 4; i++) {
                uint32_t ad = tb + aOff + i * (16 * 80) + kb;
                ldsm4(ah[i][0], ah[i][1], ah[i][2], ah[i][3], ad);
                ldsm4(al[i][0], al[i][1], al[i][2], al[i][3], ad + TILE_B);
            }
            uint32_t bh[4][2], bl[4][2];
#pragma unroll
            for (int j2 = 0; j2 < 2; j2++) {
                uint32_t bd = tb + 2 * TILE_B + bOff + j2 * (16 * 80) + kb;
                uint32_t t0, t1, t2, t3;
                ldsm4(t0, t1, t2, t3, bd);
                bh[j2 * 2][0] = t0; bh[j2 * 2][1] = t1;
                bh[j2 * 2 + 1][0] = t2; bh[j2 * 2 + 1][1] = t3;
                ldsm4(t0, t1, t2, t3, bd + TILE_B);
                bl[j2 * 2][0] = t0; bl[j2 * 2][1] = t1;
                bl[j2 * 2 + 1][0] = t2; bl[j2 * 2 + 1][1] = t3;
            }
#pragma unroll
            for (int i = 0; i < 4; i++)
#pragma unroll
                for (int j = 0; j < 4; j++) {
                    mma_bf16(acc[i][j], ah[i], bh[j]);
                    mma_bf16(acc[i][j], ah[i], bl[j]);
                    mma_bf16(acc[i][j], al[i], bh[j]);
                }
        }
        __syncthreads();
    }

    // epilogue: bias + store (C frag: rows lane/4, lane/4+8; cols (lane%4)*2)
#pragma unroll
    for (int i = 0; i < 4; i++) {
        int r0 = rowBase + warpM * 64 + i * 16 + (lane >> 2);
#pragma unroll
        for (int rr = 0; rr < 2; rr++) {
            int grow = r0 + rr * 8;
            if (grow >= nrows) continue;
#pragma unroll
            for (int j = 0; j < 4; j++) {
                int gc = colBase + warpN * 32 + j * 8 + (lane & 3) * 2;
                float2 o;
                o.x = acc[i][j][rr * 2 + 0] + bias[gc + 0];
                o.y = acc[i][j][rr * 2 + 1] + bias[gc + 1];
                *reinterpret_cast<float2*>(Cout + (size_t)grow * ldo + gc) = o;
            }
        }
    }
}

// ---------------- split prep kernels (bf16 hi/lo) ----------------
__global__ void split_a(const float* __restrict__ src, int srcStride, int cols, int applyElu,
                        __nv_bfloat16* __restrict__ hi, __nv_bfloat16* __restrict__ lo)
{
    size_t i = (size_t)blockIdx.x * blockDim.x + threadIdx.x;
    if (i >= (size_t)NN * cols) return;
    int r = (int)(i / cols), c = (int)(i % cols);
    float v = src[(size_t)r * srcStride + c];
    if (applyElu) v = v > 0.f ? v : expm1f(v);
    __nv_bfloat16 h = __float2bfloat16_rn(v);
    hi[i] = h;
    lo[i] = __float2bfloat16_rn(v - __bfloat162float(h));
}

// transpose W[K, Mout] -> Bh/Bl[(rowOff+n), k] (stride KMAX); concat bias.
__global__ void split_b(const float* __restrict__ W, const float* __restrict__ b,
                        int K, int Mout, int rowOff,
                        __nv_bfloat16* __restrict__ Bh, __nv_bfloat16* __restrict__ Bl,
                        float* __restrict__ bias)
{
    int i = blockIdx.x * blockDim.x + threadIdx.x;
    if (i >= K * Mout) return;
    int k = i / Mout, n = i % Mout;
    float v = W[i];
    __nv_bfloat16 h = __float2bfloat16_rn(v);
    size_t o = (size_t)(rowOff + n) * KMAX + k;
    Bh[o] = h;
    Bl[o] = __float2bfloat16_rn(v - __bfloat162float(h));
    if (k == 0) bias[rowOff + n] = b[n];
}

// ---------------- attention ----------------
__device__ __forceinline__ unsigned fenc(float f) {
    unsigned u = __float_as_uint(f);
    return (u & 0x80000000u) ? ~u : (u | 0x80000000u);
}
__device__ __forceinline__ float fdec(unsigned e) {
    return (e & 0x80000000u) ? __uint_as_float(e ^ 0x80000000u) : __uint_as_float(~e);
}

__global__ void init_ms(unsigned* __restrict__ m, float* __restrict__ s, int n) {
    int i = blockIdx.x * blockDim.x + threadIdx.x;
    if (i < n) { m[i] = 0x007FFFFFu; s[i] = 0.f; }   // fenc(-inf)
}

__global__ __launch_bounds__(128) void edge_alpha(
    const float* __restrict__ qk, int stride, int qOff, int kOff,
    const int* __restrict__ ei, float* __restrict__ alpha, unsigned* __restrict__ mmax)
{
    int e = blockIdx.x;
    int w = threadIdx.x >> 5, lane = threadIdx.x & 31;
    int src = ei[e], dst = ei[EE + e];
    float4 a4 = reinterpret_cast<const float4*>(qk + (size_t)dst * stride + qOff + w * CC)[lane];
    float4 b4 = reinterpret_cast<const float4*>(qk + (size_t)src * stride + kOff + w * CC)[lane];
    float s = a4.x * b4.x + a4.y * b4.y + a4.z * b4.z + a4.w * b4.w;
#pragma unroll
    for (int off = 16; off; off >>= 1) s += __shfl_xor_sync(0xFFFFFFFFu, s, off);
    if (lane == 0) {
        s *= 0.08838834764831845f;  // 1/sqrt(128)
        alpha[(size_t)e * HH + w] = s;
        atomicMax(&mmax[(size_t)dst * HH + w], fenc(s));
    }
}

__global__ void edge_expsum(const int* __restrict__ ei, float* __restrict__ alpha,
                            const unsigned* __restrict__ mmax, float* __restrict__ ssum)
{
    int i = blockIdx.x * blockDim.x + threadIdx.x;
    if (i >= EE * HH) return;
    int e = i >> 2, h = i & 3;
    int dst = ei[EE + e];
    float m = fdec(mmax[(size_t)dst * HH + h]);
    float ex = expf(alpha[i] - m);
    alpha[i] = ex;
    atomicAdd(&ssum[(size_t)dst * HH + h], ex);
}

__global__ __launch_bounds__(128) void edge_scatter(
    const float* __restrict__ vbase, int strideIn, int vOff,
    const int* __restrict__ ei, const float* __restrict__ alpha, const float* __restrict__ ssum,
    float* __restrict__ outBase, int strideOut, int outOff, int concat)
{
    int e = blockIdx.x;
    int w = threadIdx.x >> 5, lane = threadIdx.x & 31;
    int src = ei[e], dst = ei[EE + e];
    float a = alpha[(size_t)e * HH + w] / (ssum[(size_t)dst * HH + w] + EPS);
    float4 vv = reinterpret_cast<const float4*>(vbase + (size_t)src * strideIn + vOff + w * CC)[lane];
    float* o;
    if (concat) {
        o = outBase + (size_t)dst * strideOut + outOff + w * CC + lane * 4;
    } else {
        a *= 0.25f;  // mean over H=4 heads
        o = outBase + (size_t)dst * strideOut + outOff + lane * 4;
    }
    atomicAdd(o + 0, a * vv.x);
    atomicAdd(o + 1, a * vv.y);
    atomicAdd(o + 2, a * vv.z);
    atomicAdd(o + 3, a * vv.w);
}

__global__ void elu_strided(float* __restrict__ p, int stride, int off, int cols) {
    size_t i = (size_t)blockIdx.x * blockDim.x + threadIdx.x;
    if (i >= (size_t)NN * cols) return;
    int r = (int)(i / cols), c = (int)(i % cols);
    float* q = p + (size_t)r * stride + off + c;
    float v = *q;
    *q = v > 0.f ? v : expm1f(v);
}

// ---------------- pooling + head ----------------
__global__ void zero_pool(float* __restrict__ pool, float* __restrict__ cnt) {
    int i = blockIdx.x * blockDim.x + threadIdx.x;
    if (i < GG * CC) pool[i] = 0.f;
    if (i < GG) cnt[i] = 0.f;
}

__global__ __launch_bounds__(128) void pool_k(
    const float* __restrict__ h, int stride, int off, const int* __restrict__ batch,
    float* __restrict__ pool, float* __restrict__ cnt)
{
    int i = blockIdx.x;
    int g = batch[i];
    int c = threadIdx.x;
    atomicAdd(&pool[(size_t)g * CC + c], h[(size_t)i * stride + off + c]);
    if (c == 0) atomicAdd(&cnt[g], 1.f);
}

__global__ __launch_bounds__(128) void head_k(
    const float* __restrict__ pool, const float* __restrict__ cnt,
    const float* __restrict__ Wfc, const float* __restrict__ bfc,
    float* __restrict__ out)
{
    int g = blockIdx.x, t = threadIdx.x;
    __shared__ float sm[CC];
    __shared__ float logits[NCLS];
    float cv = fmaxf(cnt[g], 1.f);
    sm[t] = pool[(size_t)g * CC + t] / cv;
    __syncthreads();
    if (t < NCLS) {
        float acc = bfc[t];
#pragma unroll 4
        for (int c = 0; c < CC; c++) acc += sm[c] * Wfc[c * NCLS + t];
        logits[t] = acc;
    }
    __syncthreads();
    if (t == 0) {
        float mx = -1e30f;
#pragma unroll
        for (int j = 0; j < NCLS; j++) mx = fmaxf(mx, logits[j]);
        float ssum = 0.f;
#pragma unroll
        for (int j = 0; j < NCLS; j++) ssum += expf(logits[j] - mx);
        float lse = mx + logf(ssum);
#pragma unroll
        for (int j = 0; j < NCLS; j++) out[g * NCLS + j] = logits[j] - lse;
    }
}

// ---------------- launch ----------------
extern "C" void kernel_launch(void* const* d_in, const int* in_sizes, int n_in,
                              void* d_out, int out_size)
{
    const float* x     = (const float*)d_in[0];
    const int*   ei    = (const int*)d_in[1];
    const int*   batch = (const int*)d_in[2];
    const float* Wq1 = (const float*)d_in[3];  const float* bq1 = (const float*)d_in[4];
    const float* Wk1 = (const float*)d_in[5];  const float* bk1 = (const float*)d_in[6];
    const float* Wv1 = (const float*)d_in[7];  const float* bv1 = (const float*)d_in[8];
    const float* Ws1 = (const float*)d_in[9];  const float* bs1 = (const float*)d_in[10];
    const float* Wq2 = (const float*)d_in[11]; const float* bq2 = (const float*)d_in[12];
    const float* Wk2 = (const float*)d_in[13]; const float* bk2 = (const float*)d_in[14];
    const float* Wv2 = (const float*)d_in[15]; const float* bv2 = (const float*)d_in[16];
    const float* Ws2 = (const float*)d_in[17]; const float* bs2 = (const float*)d_in[18];
    const float* Wfc = (const float*)d_in[19]; const float* bfc = (const float*)d_in[20];
    float* out = (float*)d_out;

    float *qkvs1, *qkvs2, *bias, *alpha, *s, *pool, *cnt;
    __nv_bfloat16 *Ah, *Al, *Bh, *Bl;
    unsigned* m;
    cudaGetSymbolAddress((void**)&qkvs1, g_qkvs1);
    cudaGetSymbolAddress((void**)&qkvs2, g_qkvs2);
    cudaGetSymbolAddress((void**)&Ah, g_Ah);
    cudaGetSymbolAddress((void**)&Al, g_Al);
    cudaGetSymbolAddress((void**)&Bh, g_Bh);
    cudaGetSymbolAddress((void**)&Bl, g_Bl);
    cudaGetSymbolAddress((void**)&bias, g_biasv);
    cudaGetSymbolAddress((void**)&alpha, g_alpha);
    cudaGetSymbolAddress((void**)&m, g_m);
    cudaGetSymbolAddress((void**)&s, g_s);
    cudaGetSymbolAddress((void**)&pool, g_pool);
    cudaGetSymbolAddress((void**)&cnt, g_cnt);

    cudaFuncSetAttribute(gemm_bf16x3, cudaFuncAttributeMaxDynamicSharedMemorySize, SMEM_GEMM);

    const int rowBlocks = (NN + 127) / 128;   // 391

    // ---------- layer 1 prep ----------
    int nb1 = (FF * 512 + 255) / 256;
    split_b<<<nb1, 256>>>(Wq1, bq1, FF, 512, 0,    Bh, Bl, bias);
    split_b<<<nb1, 256>>>(Wk1, bk1, FF, 512, 512,  Bh, Bl, bias);
    split_b<<<nb1, 256>>>(Wv1, bv1, FF, 512, 1024, Bh, Bl, bias);
    split_b<<<nb1, 256>>>(Ws1, bs1, FF, 512, 1536, Bh, Bl, bias);
    split_a<<<(int)(((size_t)NN * FF + 255) / 256), 256>>>(x, FF, FF, 0, Ah, Al);

    // ---------- layer 1 fused GEMM: qkvs1 = [q|k|v|skip] ----------
    gemm_bf16x3<<<dim3(N1 / 128, rowBlocks), 256, SMEM_GEMM>>>(
        Ah, Al, FF, FF, Bh, Bl, bias, qkvs1, N1, NN);

    // ---------- layer 1 attention ----------
    init_ms<<<(NN * HH + 255) / 256, 256>>>(m, s, NN * HH);
    edge_alpha<<<EE, 128>>>(qkvs1, N1, 0, 512, ei, alpha, m);
    edge_expsum<<<(EE * HH + 255) / 256, 256>>>(ei, alpha, m, s);
    edge_scatter<<<EE, 128>>>(qkvs1, N1, 1024, ei, alpha, s, qkvs1, N1, 1536, 1);

    // ---------- layer 2 prep (ELU fused into A split) ----------
    split_a<<<(int)(((size_t)NN * 512 + 255) / 256), 256>>>(qkvs1 + 1536, N1, 512, 1, Ah, Al);
    int nb2 = (512 * 512 + 255) / 256;
    split_b<<<nb2, 256>>>(Wq2, bq2, 512, 512, 0,    Bh, Bl, bias);
    split_b<<<nb2, 256>>>(Wk2, bk2, 512, 512, 512,  Bh, Bl, bias);
    split_b<<<nb2, 256>>>(Wv2, bv2, 512, 512, 1024, Bh, Bl, bias);
    split_b<<<(512 * 128 + 255) / 256, 256>>>(Ws2, bs2, 512, 128, 1536, Bh, Bl, bias);

    // ---------- layer 2 fused GEMM: qkvs2 = [q|k|v|skip] ----------
    gemm_bf16x3<<<dim3(N2 / 128, rowBlocks), 256, SMEM_GEMM>>>(
        Ah, Al, 512, 512, Bh, Bl, bias, qkvs2, N2, NN);

    // ---------- layer 2 attention ----------
    init_ms<<<(NN * HH + 255) / 256, 256>>>(m, s, NN * HH);
    edge_alpha<<<EE, 128>>>(qkvs2, N2, 0, 512, ei, alpha, m);
    edge_expsum<<<(EE * HH + 255) / 256, 256>>>(ei, alpha, m, s);
    edge_scatter<<<EE, 128>>>(qkvs2, N2, 1024, ei, alpha, s, qkvs2, N2, 1536, 0);
    elu_strided<<<(int)(((size_t)NN * CC + 255) / 256), 256>>>(qkvs2, N2, 1536, CC);

    // ---------- pooling + classifier ----------
    zero_pool<<<(GG * CC + 255) / 256, 256>>>(pool, cnt);
    pool_k<<<NN, 128>>>(qkvs2, N2, 1536, batch, pool, cnt);
    head_k<<<GG, 128>>>(pool, cnt, Wfc, bfc, out);
}

// round 4
// speedup vs baseline: 2.2655x; 1.2176x over previous
#include <cuda_runtime.h>
#include <cuda_bf16.h>
#include <cstdint>
#include <cstddef>

// ---------------- problem dims ----------------
#define NN 50000
#define FF 256
#define EE 200000
#define HH 4
#define CC 128
#define GG 256
#define NCLS 10
#define EPS 1e-16f

#define N1 2048            // layer1 fused output cols: q|k|v|skip (4*512)
#define N2 1664            // layer2 fused output cols: q|k|v (3*512) | skip (128)
#define KMAX 512
#define NB 391             // ceil(NN/128)

// ---------------- scratch (device globals) ----------------
__device__ __align__(256) float         g_qkvs1[(size_t)NN * N1];
__device__ __align__(256) float         g_qkvs2[(size_t)NN * N2];
__device__ __align__(256) __nv_bfloat16 g_Ah[(size_t)NN * KMAX];
__device__ __align__(256) __nv_bfloat16 g_Al[(size_t)NN * KMAX];
__device__ __align__(256) __nv_bfloat16 g_Bh[(size_t)N1 * KMAX];
__device__ __align__(256) __nv_bfloat16 g_Bl[(size_t)N1 * KMAX];
__device__ __align__(256) float         g_biasv[N1];
__device__ __align__(256) float         g_alpha[(size_t)EE * HH];
__device__ __align__(256) int           g_cnt[NN];
__device__ __align__(256) int           g_bsum[512];
__device__ __align__(256) int           g_rowptr[NN + 1];
__device__ __align__(256) int           g_cur[NN];
__device__ __align__(256) int           g_csrsrc[EE];
__device__ __align__(256) float         g_pool[GG * CC];
__device__ __align__(256) float         g_cnt_g[GG];

// ---------------- PTX helpers (sm_80-generic) ----------------
__device__ __forceinline__ uint32_t smem_u32(const void* p) {
    uint32_t a;
    asm("{ .reg .u64 t; cvta.to.shared.u64 t, %1; cvt.u32.u64 %0, t; }" : "=r"(a) : "l"(p));
    return a;
}
__device__ __forceinline__ void cp16(uint32_t dst, const void* src, unsigned srcsz) {
    asm volatile("cp.async.cg.shared.global [%0], [%1], 16, %2;"
                 :: "r"(dst), "l"(src), "r"(srcsz) : "memory");
}
__device__ __forceinline__ void ldsm4(uint32_t& r0, uint32_t& r1, uint32_t& r2, uint32_t& r3,
                                      uint32_t a) {
    asm volatile("ldmatrix.sync.aligned.m8n8.x4.shared.b16 {%0,%1,%2,%3}, [%4];"
                 : "=r"(r0), "=r"(r1), "=r"(r2), "=r"(r3) : "r"(a));
}
__device__ __forceinline__ void mma_bf16(float* c, const uint32_t* a, const uint32_t* b) {
    asm volatile(
        "mma.sync.aligned.m16n8k16.row.col.f32.bf16.bf16.f32 "
        "{%0,%1,%2,%3}, {%4,%5,%6,%7}, {%8,%9}, {%0,%1,%2,%3};"
        : "+f"(c[0]), "+f"(c[1]), "+f"(c[2]), "+f"(c[3])
        : "r"(a[0]), "r"(a[1]), "r"(a[2]), "r"(a[3]), "r"(b[0]), "r"(b[1]));
}

// ---------------- bf16x3 tensor-core GEMM (3-stage cp.async) ----------------
#define TILE_B   (128 * 80)               // 10240 B per 128x32 bf16 tile (80B row pad)
#define STAGE_B  (4 * TILE_B)             // Ah,Al,Bh,Bl = 40960 B per stage
#define SMEM_GEMM (3 * STAGE_B)           // 122880 B

__global__ __launch_bounds__(256, 1)
void gemm_bf16x3(const __nv_bfloat16* __restrict__ Ahb, const __nv_bfloat16* __restrict__ Alb,
                 int lda, int K,
                 const __nv_bfloat16* __restrict__ Bhb, const __nv_bfloat16* __restrict__ Blb,
                 const float* __restrict__ bias, float* __restrict__ Cout, int ldo, int nrows)
{
    extern __shared__ char smem[];
    const uint32_t sb = smem_u32(smem);
    const int tid = threadIdx.x;
    const int lane = tid & 31;
    const int wid = tid >> 5;
    const int warpM = wid & 1;
    const int warpN = wid >> 1;
    const int rowBase = blockIdx.y * 128;
    const int colBase = blockIdx.x * 128;

    float acc[4][4][4];
#pragma unroll
    for (int i = 0; i < 4; i++)
#pragma unroll
        for (int j = 0; j < 4; j++)
#pragma unroll
            for (int f = 0; f < 4; f++) acc[i][j][f] = 0.f;

    const int T = K >> 5;

    auto loadStage = [&](int s, int k0) {
        uint32_t base = sb + s * STAGE_B;
#pragma unroll
        for (int t = 0; t < 2; t++) {
            int c = tid + t * 256;
            int r = c >> 2;
            int q = c & 3;
            uint32_t soff = (uint32_t)(r * 80 + q * 16);
            int ga = rowBase + r;
            unsigned va = (ga < nrows) ? 16u : 0u;
            int gac = (ga < nrows) ? ga : (nrows - 1);
            size_t aoff = (size_t)gac * lda + k0 + q * 8;
            cp16(base + soff,              Ahb + aoff, va);
            cp16(base + TILE_B + soff,     Alb + aoff, va);
            size_t boff = (size_t)(colBase + r) * KMAX + k0 + q * 8;
            cp16(base + 2 * TILE_B + soff, Bhb + boff, 16u);
            cp16(base + 3 * TILE_B + soff, Blb + boff, 16u);
        }
        asm volatile("cp.async.commit_group;" ::: "memory");
    };

    const uint32_t aOff = (uint32_t)((warpM * 64 + (lane & 15)) * 80 + (lane >> 4) * 16);
    const uint32_t bOff = (uint32_t)((warpN * 32 + (lane & 7) + ((lane >> 4) & 1) * 8) * 80
                                     + ((lane >> 3) & 1) * 16);

    loadStage(0, 0);
    loadStage(1, 32);

    int s = 0;
    for (int it = 0; it < T; it++) {
        if (it + 2 < T) loadStage((it + 2) % 3, (it + 2) << 5);
        int rem = T - 1 - it;
        if (rem >= 2)      asm volatile("cp.async.wait_group 2;" ::: "memory");
        else if (rem == 1) asm volatile("cp.async.wait_group 1;" ::: "memory");
        else               asm volatile("cp.async.wait_group 0;" ::: "memory");
        __syncthreads();

        uint32_t tb = sb + s * STAGE_B;
#pragma unroll
        for (int ks = 0; ks < 2; ks++) {
            uint32_t kb = ks * 32;
            uint32_t ah[4][4], al[4][4];
#pragma unroll
            for (int i = 0; i < 4; i++) {
                uint32_t ad = tb + aOff + i * (16 * 80) + kb;
                ldsm4(ah[i][0], ah[i][1], ah[i][2], ah[i][3], ad);
                ldsm4(al[i][0], al[i][1], al[i][2], al[i][3], ad + TILE_B);
            }
            uint32_t bh[4][2], bl[4][2];
#pragma unroll
            for (int j2 = 0; j2 < 2; j2++) {
                uint32_t bd = tb + 2 * TILE_B + bOff + j2 * (16 * 80) + kb;
                uint32_t t0, t1, t2, t3;
                ldsm4(t0, t1, t2, t3, bd);
                bh[j2 * 2][0] = t0; bh[j2 * 2][1] = t1;
                bh[j2 * 2 + 1][0] = t2; bh[j2 * 2 + 1][1] = t3;
                ldsm4(t0, t1, t2, t3, bd + TILE_B);
                bl[j2 * 2][0] = t0; bl[j2 * 2][1] = t1;
                bl[j2 * 2 + 1][0] = t2; bl[j2 * 2 + 1][1] = t3;
            }
#pragma unroll
            for (int i = 0; i < 4; i++)
#pragma unroll
                for (int j = 0; j < 4; j++) {
                    mma_bf16(acc[i][j], ah[i], bh[j]);
                    mma_bf16(acc[i][j], ah[i], bl[j]);
                    mma_bf16(acc[i][j], al[i], bh[j]);
                }
        }
        __syncthreads();
        s++; if (s == 3) s = 0;
    }

#pragma unroll
    for (int i = 0; i < 4; i++) {
        int r0 = rowBase + warpM * 64 + i * 16 + (lane >> 2);
#pragma unroll
        for (int rr = 0; rr < 2; rr++) {
            int grow = r0 + rr * 8;
            if (grow >= nrows) continue;
#pragma unroll
            for (int j = 0; j < 4; j++) {
                int gc = colBase + warpN * 32 + j * 8 + (lane & 3) * 2;
                float2 o;
                o.x = acc[i][j][rr * 2 + 0] + bias[gc + 0];
                o.y = acc[i][j][rr * 2 + 1] + bias[gc + 1];
                *reinterpret_cast<float2*>(Cout + (size_t)grow * ldo + gc) = o;
            }
        }
    }
}

// ---------------- split prep ----------------
__global__ void split_a(const float* __restrict__ src, int srcStride, int cols, int applyElu,
                        __nv_bfloat16* __restrict__ hi, __nv_bfloat16* __restrict__ lo)
{
    size_t i = (size_t)blockIdx.x * blockDim.x + threadIdx.x;
    if (i >= (size_t)NN * cols) return;
    int r = (int)(i / cols), c = (int)(i % cols);
    float v = src[(size_t)r * srcStride + c];
    if (applyElu) v = v > 0.f ? v : expm1f(v);
    __nv_bfloat16 h = __float2bfloat16_rn(v);
    hi[i] = h;
    lo[i] = __float2bfloat16_rn(v - __bfloat162float(h));
}

// coalesced tiled transpose split: W[K, Mout] -> Bh/Bl[(rowOff+n)*KMAX + k]
__global__ void split_bT(const float* __restrict__ W, const float* __restrict__ b,
                         int K, int Mout, int rowOff,
                         __nv_bfloat16* __restrict__ Bh, __nv_bfloat16* __restrict__ Bl,
                         float* __restrict__ bias)
{
    __shared__ float tile[32][33];
    int nb = blockIdx.x * 32, kb = blockIdx.y * 32;
    int tx = threadIdx.x, ty = threadIdx.y;   // block (32, 8)
#pragma unroll
    for (int i = 0; i < 4; i++) {
        int k = kb + ty + i * 8;
        if (k < K && nb + tx < Mout) tile[ty + i * 8][tx] = W[(size_t)k * Mout + nb + tx];
    }
    __syncthreads();
#pragma unroll
    for (int i = 0; i < 4; i++) {
        int n = nb + ty + i * 8, k = kb + tx;
        if (n < Mout && k < K) {
            float v = tile[tx][ty + i * 8];
            __nv_bfloat16 h = __float2bfloat16_rn(v);
            size_t o = (size_t)(rowOff + n) * KMAX + k;
            Bh[o] = h;
            Bl[o] = __float2bfloat16_rn(v - __bfloat162float(h));
        }
    }
    if (ty == 0 && blockIdx.y == 0 && nb + tx < Mout) bias[rowOff + nb + tx] = b[nb + tx];
}

// ---------------- CSR build ----------------
__global__ void zero_cnt(int* __restrict__ c) {
    int i = blockIdx.x * blockDim.x + threadIdx.x;
    if (i < NN) c[i] = 0;
}
__global__ void hist_dst(const int* __restrict__ ei, int* __restrict__ cnt) {
    int i = blockIdx.x * blockDim.x + threadIdx.x;
    if (i < EE) atomicAdd(&cnt[ei[EE + i]], 1);
}
__global__ void blocksum(const int* __restrict__ cnt, int* __restrict__ bsum) {
    __shared__ int sm[128];
    int idx = blockIdx.x * 128 + threadIdx.x;
    sm[threadIdx.x] = (idx < NN) ? cnt[idx] : 0;
    __syncthreads();
#pragma unroll
    for (int off = 64; off; off >>= 1) {
        if (threadIdx.x < off) sm[threadIdx.x] += sm[threadIdx.x + off];
        __syncthreads();
    }
    if (threadIdx.x == 0) bsum[blockIdx.x] = sm[0];
}
__global__ void scan_bsum(int* __restrict__ bsum, int* __restrict__ rowptr) {
    __shared__ int sm[512];
    int t = threadIdx.x;
    int v = (t < NB) ? bsum[t] : 0;
    sm[t] = v;
    __syncthreads();
#pragma unroll
    for (int off = 1; off < 512; off <<= 1) {
        int x = (t >= off) ? sm[t - off] : 0;
        __syncthreads();
        sm[t] += x;
        __syncthreads();
    }
    if (t < NB) bsum[t] = sm[t] - v;       // exclusive
    if (t == 0) rowptr[NN] = EE;
}
__global__ void write_rowptr(const int* __restrict__ cnt, const int* __restrict__ bsum,
                             int* __restrict__ rowptr, int* __restrict__ cur) {
    __shared__ int sm[128];
    int b = blockIdx.x, t = threadIdx.x;
    int idx = b * 128 + t;
    int v = (idx < NN) ? cnt[idx] : 0;
    sm[t] = v;
    __syncthreads();
#pragma unroll
    for (int off = 1; off < 128; off <<= 1) {
        int x = (t >= off) ? sm[t - off] : 0;
        __syncthreads();
        sm[t] += x;
        __syncthreads();
    }
    if (idx < NN) {
        int r = bsum[b] + sm[t] - v;
        rowptr[idx] = r;
        cur[idx] = r;
    }
}
__global__ void fill_csr(const int* __restrict__ ei, int* __restrict__ cur,
                         int* __restrict__ csrsrc) {
    int i = blockIdx.x * blockDim.x + threadIdx.x;
    if (i >= EE) return;
    int pos = atomicAdd(&cur[ei[EE + i]], 1);
    csrsrc[pos] = ei[i];
}

// ---------------- fused per-node attention ----------------
// block = dst node, warp = head. Pass1: scores + max. Pass2: exp, sum, weighted V.
// mode 0: concat -> out[n, outOff + h*CC + c] = skip + msg
// mode 1: mean over heads + ELU -> out[n, outOff + c]
__global__ __launch_bounds__(128) void att_fused(
    const float* __restrict__ qkv, int stride, int qOff, int kOff, int vOff,
    const int* __restrict__ rowptr, const int* __restrict__ csrsrc,
    float* __restrict__ alpha,
    float* __restrict__ outp, int strideOut, int outOff, int mode)
{
    int n = blockIdx.x;
    int h = threadIdx.x >> 5, lane = threadIdx.x & 31;
    int r0 = rowptr[n], r1 = rowptr[n + 1];

    const float4 q4 = *reinterpret_cast<const float4*>(
        qkv + (size_t)n * stride + qOff + h * CC + lane * 4);

    float m = -3.0e38f;
    for (int j = r0; j < r1; j++) {
        int src = csrsrc[j];
        float4 k4 = *reinterpret_cast<const float4*>(
            qkv + (size_t)src * stride + kOff + h * CC + lane * 4);
        float d = q4.x * k4.x + q4.y * k4.y + q4.z * k4.z + q4.w * k4.w;
#pragma unroll
        for (int o = 16; o; o >>= 1) d += __shfl_xor_sync(0xFFFFFFFFu, d, o);
        d *= 0.08838834764831845f;     // 1/sqrt(128)
        m = fmaxf(m, d);
        if (lane == 0) alpha[(size_t)j * HH + h] = d;
    }
    __syncwarp();

    float s = 0.f;
    float4 acc = make_float4(0.f, 0.f, 0.f, 0.f);
    for (int j = r0; j < r1; j++) {
        int src = csrsrc[j];
        float e = __expf(alpha[(size_t)j * HH + h] - m);
        s += e;
        float4 v4 = *reinterpret_cast<const float4*>(
            qkv + (size_t)src * stride + vOff + h * CC + lane * 4);
        acc.x += e * v4.x; acc.y += e * v4.y; acc.z += e * v4.z; acc.w += e * v4.w;
    }
    float inv = 1.f / (s + EPS);

    if (mode == 0) {
        float* o = outp + (size_t)n * strideOut + outOff + h * CC + lane * 4;
        float4 sk = *reinterpret_cast<float4*>(o);
        sk.x += acc.x * inv; sk.y += acc.y * inv;
        sk.z += acc.z * inv; sk.w += acc.w * inv;
        *reinterpret_cast<float4*>(o) = sk;
    } else {
        __shared__ float sm[HH][CC];
        float qsc = inv * 0.25f;
        sm[h][lane * 4 + 0] = acc.x * qsc;
        sm[h][lane * 4 + 1] = acc.y * qsc;
        sm[h][lane * 4 + 2] = acc.z * qsc;
        sm[h][lane * 4 + 3] = acc.w * qsc;
        __syncthreads();
        int c = threadIdx.x;
        float val = sm[0][c] + sm[1][c] + sm[2][c] + sm[3][c];
        float* o = outp + (size_t)n * strideOut + outOff + c;
        float r = *o + val;
        *o = r > 0.f ? r : expm1f(r);     // fused ELU (layer 2)
    }
}

// ---------------- pooling + head ----------------
__global__ void zero_pool(float* __restrict__ pool, float* __restrict__ cnt) {
    int i = blockIdx.x * blockDim.x + threadIdx.x;
    if (i < GG * CC) pool[i] = 0.f;
    if (i < GG) cnt[i] = 0.f;
}
__global__ __launch_bounds__(128) void pool_k(
    const float* __restrict__ h, int stride, int off, const int* __restrict__ batch,
    float* __restrict__ pool, float* __restrict__ cnt)
{
    int i = blockIdx.x;
    int g = batch[i];
    int c = threadIdx.x;
    atomicAdd(&pool[(size_t)g * CC + c], h[(size_t)i * stride + off + c]);
    if (c == 0) atomicAdd(&cnt[g], 1.f);
}
__global__ __launch_bounds__(128) void head_k(
    const float* __restrict__ pool, const float* __restrict__ cnt,
    const float* __restrict__ Wfc, const float* __restrict__ bfc,
    float* __restrict__ out)
{
    int g = blockIdx.x, t = threadIdx.x;
    __shared__ float sm[CC];
    __shared__ float logits[NCLS];
    float cv = fmaxf(cnt[g], 1.f);
    sm[t] = pool[(size_t)g * CC + t] / cv;
    __syncthreads();
    if (t < NCLS) {
        float acc = bfc[t];
#pragma unroll 4
        for (int c = 0; c < CC; c++) acc += sm[c] * Wfc[c * NCLS + t];
        logits[t] = acc;
    }
    __syncthreads();
    if (t == 0) {
        float mx = -1e30f;
#pragma unroll
        for (int j = 0; j < NCLS; j++) mx = fmaxf(mx, logits[j]);
        float ssum = 0.f;
#pragma unroll
        for (int j = 0; j < NCLS; j++) ssum += expf(logits[j] - mx);
        float lse = mx + logf(ssum);
#pragma unroll
        for (int j = 0; j < NCLS; j++) out[g * NCLS + j] = logits[j] - lse;
    }
}

// ---------------- launch ----------------
extern "C" void kernel_launch(void* const* d_in, const int* in_sizes, int n_in,
                              void* d_out, int out_size)
{
    const float* x     = (const float*)d_in[0];
    const int*   ei    = (const int*)d_in[1];
    const int*   batch = (const int*)d_in[2];
    const float* Wq1 = (const float*)d_in[3];  const float* bq1 = (const float*)d_in[4];
    const float* Wk1 = (const float*)d_in[5];  const float* bk1 = (const float*)d_in[6];
    const float* Wv1 = (const float*)d_in[7];  const float* bv1 = (const float*)d_in[8];
    const float* Ws1 = (const float*)d_in[9];  const float* bs1 = (const float*)d_in[10];
    const float* Wq2 = (const float*)d_in[11]; const float* bq2 = (const float*)d_in[12];
    const float* Wk2 = (const float*)d_in[13]; const float* bk2 = (const float*)d_in[14];
    const float* Wv2 = (const float*)d_in[15]; const float* bv2 = (const float*)d_in[16];
    const float* Ws2 = (const float*)d_in[17]; const float* bs2 = (const float*)d_in[18];
    const float* Wfc = (const float*)d_in[19]; const float* bfc = (const float*)d_in[20];
    float* out = (float*)d_out;

    float *qkvs1, *qkvs2, *bias, *alpha, *pool, *cntg;
    __nv_bfloat16 *Ah, *Al, *Bh, *Bl;
    int *cnt, *bsum, *rowptr, *cur, *csrsrc;
    cudaGetSymbolAddress((void**)&qkvs1, g_qkvs1);
    cudaGetSymbolAddress((void**)&qkvs2, g_qkvs2);
    cudaGetSymbolAddress((void**)&Ah, g_Ah);
    cudaGetSymbolAddress((void**)&Al, g_Al);
    cudaGetSymbolAddress((void**)&Bh, g_Bh);
    cudaGetSymbolAddress((void**)&Bl, g_Bl);
    cudaGetSymbolAddress((void**)&bias, g_biasv);
    cudaGetSymbolAddress((void**)&alpha, g_alpha);
    cudaGetSymbolAddress((void**)&cnt, g_cnt);
    cudaGetSymbolAddress((void**)&bsum, g_bsum);
    cudaGetSymbolAddress((void**)&rowptr, g_rowptr);
    cudaGetSymbolAddress((void**)&cur, g_cur);
    cudaGetSymbolAddress((void**)&csrsrc, g_csrsrc);
    cudaGetSymbolAddress((void**)&pool, g_pool);
    cudaGetSymbolAddress((void**)&cntg, g_cnt_g);

    cudaFuncSetAttribute(gemm_bf16x3, cudaFuncAttributeMaxDynamicSharedMemorySize, SMEM_GEMM);

    dim3 tb(32, 8);

    // ---------- CSR build (once, reused by both layers) ----------
    zero_cnt<<<(NN + 255) / 256, 256>>>(cnt);
    hist_dst<<<(EE + 255) / 256, 256>>>(ei, cnt);
    blocksum<<<NB, 128>>>(cnt, bsum);
    scan_bsum<<<1, 512>>>(bsum, rowptr);
    write_rowptr<<<NB, 128>>>(cnt, bsum, rowptr, cur);
    fill_csr<<<(EE + 255) / 256, 256>>>(ei, cur, csrsrc);

    // ---------- layer 1 prep ----------
    split_bT<<<dim3(512 / 32, FF / 32), tb>>>(Wq1, bq1, FF, 512, 0,    Bh, Bl, bias);
    split_bT<<<dim3(512 / 32, FF / 32), tb>>>(Wk1, bk1, FF, 512, 512,  Bh, Bl, bias);
    split_bT<<<dim3(512 / 32, FF / 32), tb>>>(Wv1, bv1, FF, 512, 1024, Bh, Bl, bias);
    split_bT<<<dim3(512 / 32, FF / 32), tb>>>(Ws1, bs1, FF, 512, 1536, Bh, Bl, bias);
    split_a<<<(int)(((size_t)NN * FF + 255) / 256), 256>>>(x, FF, FF, 0, Ah, Al);

    // ---------- layer 1 fused GEMM + attention ----------
    gemm_bf16x3<<<dim3(N1 / 128, NB), 256, SMEM_GEMM>>>(
        Ah, Al, FF, FF, Bh, Bl, bias, qkvs1, N1, NN);
    att_fused<<<NN, 128>>>(qkvs1, N1, 0, 512, 1024, rowptr, csrsrc, alpha,
                           qkvs1, N1, 1536, 0);

    // ---------- layer 2 prep (ELU fused into A split) ----------
    split_a<<<(int)(((size_t)NN * 512 + 255) / 256), 256>>>(qkvs1 + 1536, N1, 512, 1, Ah, Al);
    split_bT<<<dim3(512 / 32, 512 / 32), tb>>>(Wq2, bq2, 512, 512, 0,    Bh, Bl, bias);
    split_bT<<<dim3(512 / 32, 512 / 32), tb>>>(Wk2, bk2, 512, 512, 512,  Bh, Bl, bias);
    split_bT<<<dim3(512 / 32, 512 / 32), tb>>>(Wv2, bv2, 512, 512, 1024, Bh, Bl, bias);
    split_bT<<<dim3(128 / 32, 512 / 32), tb>>>(Ws2, bs2, 512, 128, 1536, Bh, Bl, bias);

    // ---------- layer 2 fused GEMM + attention (mean + ELU fused) ----------
    gemm_bf16x3<<<dim3(N2 / 128, NB), 256, SMEM_GEMM>>>(
        Ah, Al, 512, 512, Bh, Bl, bias, qkvs2, N2, NN);
    att_fused<<<NN, 128>>>(qkvs2, N2, 0, 512, 1024, rowptr, csrsrc, alpha,
                           qkvs2, N2, 1536, 1);

    // ---------- pooling + classifier ----------
    zero_pool<<<(GG * CC + 255) / 256, 256>>>(pool, cntg);
    pool_k<<<NN, 128>>>(qkvs2, N2, 1536, batch, pool, cntg);
    head_k<<<GG, 128>>>(pool, cntg, Wfc, bfc, out);
}

// round 5
// speedup vs baseline: 2.6876x; 1.1863x over previous
#include <cuda_runtime.h>
#include <cuda_bf16.h>
#include <cstdint>
#include <cstddef>

// ---------------- problem dims ----------------
#define NN 50000
#define FF 256
#define EE 200000
#define HH 4
#define CC 128
#define GG 256
#define NCLS 10
#define EPS 1e-16f

#define N1 2048            // layer1 fused output cols: q|k|v|skip (4*512)
#define N2 1664            // layer2 fused output cols: q|k|v (3*512) | skip (128)
#define KMAX 512
#define NB 391             // ceil(NN/128)

// ---------------- scratch (device globals) ----------------
__device__ __align__(256) float         g_qkvs1[(size_t)NN * N1];
__device__ __align__(256) float         g_qkvs2[(size_t)NN * N2];
__device__ __align__(256) __nv_bfloat16 g_Ah[(size_t)NN * KMAX];
__device__ __align__(256) __nv_bfloat16 g_Al[(size_t)NN * KMAX];
__device__ __align__(256) __nv_bfloat16 g_Bh[(size_t)N1 * KMAX];
__device__ __align__(256) __nv_bfloat16 g_Bl[(size_t)N1 * KMAX];
__device__ __align__(256) float         g_biasv[N1];
__device__ __align__(256) float         g_alpha[(size_t)EE * HH];
__device__ __align__(256) int           g_cnt[NN];
__device__ __align__(256) int           g_bsum[512];
__device__ __align__(256) int           g_rowptr[NN + 1];
__device__ __align__(256) int           g_cur[NN];
__device__ __align__(256) int           g_csrsrc[EE];
__device__ __align__(256) float         g_pool[GG * CC];
__device__ __align__(256) float         g_cnt_g[GG];

// ---------------- PTX helpers (sm_80-generic) ----------------
__device__ __forceinline__ uint32_t smem_u32(const void* p) {
    uint32_t a;
    asm("{ .reg .u64 t; cvta.to.shared.u64 t, %1; cvt.u32.u64 %0, t; }" : "=r"(a) : "l"(p));
    return a;
}
__device__ __forceinline__ void cp16(uint32_t dst, const void* src, unsigned srcsz) {
    asm volatile("cp.async.cg.shared.global [%0], [%1], 16, %2;"
                 :: "r"(dst), "l"(src), "r"(srcsz) : "memory");
}
__device__ __forceinline__ void ldsm4(uint32_t& r0, uint32_t& r1, uint32_t& r2, uint32_t& r3,
                                      uint32_t a) {
    asm volatile("ldmatrix.sync.aligned.m8n8.x4.shared.b16 {%0,%1,%2,%3}, [%4];"
                 : "=r"(r0), "=r"(r1), "=r"(r2), "=r"(r3) : "r"(a));
}
__device__ __forceinline__ void mma_bf16(float* c, const uint32_t* a, const uint32_t* b) {
    asm volatile(
        "mma.sync.aligned.m16n8k16.row.col.f32.bf16.bf16.f32 "
        "{%0,%1,%2,%3}, {%4,%5,%6,%7}, {%8,%9}, {%0,%1,%2,%3};"
        : "+f"(c[0]), "+f"(c[1]), "+f"(c[2]), "+f"(c[3])
        : "r"(a[0]), "r"(a[1]), "r"(a[2]), "r"(a[3]), "r"(b[0]), "r"(b[1]));
}

// ---------------- bf16x3 tensor-core GEMM (4-stage cp.async, 1 sync/iter) ----
#define TILE_B   (128 * 80)               // 10240 B per 128x32 bf16 tile (80B row pad)
#define STAGE_B  (4 * TILE_B)             // Ah,Al,Bh,Bl = 40960 B per stage
#define SMEM_GEMM (4 * STAGE_B)           // 163840 B

__global__ __launch_bounds__(256, 1)
void gemm_bf16x3(const __nv_bfloat16* __restrict__ Ahb, const __nv_bfloat16* __restrict__ Alb,
                 int lda, int K,
                 const __nv_bfloat16* __restrict__ Bhb, const __nv_bfloat16* __restrict__ Blb,
                 const float* __restrict__ bias, float* __restrict__ Cout, int ldo, int nrows)
{
    extern __shared__ char smem[];
    const uint32_t sb = smem_u32(smem);
    const int tid = threadIdx.x;
    const int lane = tid & 31;
    const int wid = tid >> 5;
    const int warpM = wid & 1;
    const int warpN = wid >> 1;
    const int rowBase = blockIdx.y * 128;
    const int colBase = blockIdx.x * 128;

    float acc[4][4][4];
#pragma unroll
    for (int i = 0; i < 4; i++)
#pragma unroll
        for (int j = 0; j < 4; j++)
#pragma unroll
            for (int f = 0; f < 4; f++) acc[i][j][f] = 0.f;

    const int T = K >> 5;

    auto loadStage = [&](int s, int k0) {
        uint32_t base = sb + s * STAGE_B;
#pragma unroll
        for (int t = 0; t < 2; t++) {
            int c = tid + t * 256;
            int r = c >> 2;
            int q = c & 3;
            uint32_t soff = (uint32_t)(r * 80 + q * 16);
            int ga = rowBase + r;
            unsigned va = (ga < nrows) ? 16u : 0u;
            int gac = (ga < nrows) ? ga : (nrows - 1);
            size_t aoff = (size_t)gac * lda + k0 + q * 8;
            cp16(base + soff,              Ahb + aoff, va);
            cp16(base + TILE_B + soff,     Alb + aoff, va);
            size_t boff = (size_t)(colBase + r) * KMAX + k0 + q * 8;
            cp16(base + 2 * TILE_B + soff, Bhb + boff, 16u);
            cp16(base + 3 * TILE_B + soff, Blb + boff, 16u);
        }
        asm volatile("cp.async.commit_group;" ::: "memory");
    };

    const uint32_t aOff = (uint32_t)((warpM * 64 + (lane & 15)) * 80 + (lane >> 4) * 16);
    const uint32_t bOff = (uint32_t)((warpN * 32 + (lane & 7) + ((lane >> 4) & 1) * 8) * 80
                                     + ((lane >> 3) & 1) * 16);

    // depth-3 pipeline over 4 stages: load blocks 0,1 up front; block it+2 inside.
    loadStage(0, 0);
    loadStage(1, 32);

    for (int it = 0; it < T; it++) {
        if (it + 2 < T) loadStage((it + 2) & 3, (it + 2) << 5);
        int pend = ((it + 2 < T) ? 2 : (it + 1 < T) ? 1 : 0);
        if (pend == 2)      asm volatile("cp.async.wait_group 2;" ::: "memory");
        else if (pend == 1) asm volatile("cp.async.wait_group 1;" ::: "memory");
        else                asm volatile("cp.async.wait_group 0;" ::: "memory");
        __syncthreads();   // single barrier: also separates consume(it-2) from rewrite(it)

        uint32_t tb = sb + (it & 3) * STAGE_B;
#pragma unroll
        for (int ks = 0; ks < 2; ks++) {
            uint32_t kb = ks * 32;
            uint32_t ah[4][4], al[4][4];
#pragma unroll
            for (int i = 0; i < 4; i++) {
                uint32_t ad = tb + aOff + i * (16 * 80) + kb;
                ldsm4(ah[i][0], ah[i][1], ah[i][2], ah[i][3], ad);
                ldsm4(al[i][0], al[i][1], al[i][2], al[i][3], ad + TILE_B);
            }
            uint32_t bh[4][2], bl[4][2];
#pragma unroll
            for (int j2 = 0; j2 < 2; j2++) {
                uint32_t bd = tb + 2 * TILE_B + bOff + j2 * (16 * 80) + kb;
                uint32_t t0, t1, t2, t3;
                ldsm4(t0, t1, t2, t3, bd);
                bh[j2 * 2][0] = t0; bh[j2 * 2][1] = t1;
                bh[j2 * 2 + 1][0] = t2; bh[j2 * 2 + 1][1] = t3;
                ldsm4(t0, t1, t2, t3, bd + TILE_B);
                bl[j2 * 2][0] = t0; bl[j2 * 2][1] = t1;
                bl[j2 * 2 + 1][0] = t2; bl[j2 * 2 + 1][1] = t3;
            }
#pragma unroll
            for (int i = 0; i < 4; i++)
#pragma unroll
                for (int j = 0; j < 4; j++) {
                    mma_bf16(acc[i][j], ah[i], bh[j]);
                    mma_bf16(acc[i][j], ah[i], bl[j]);
                    mma_bf16(acc[i][j], al[i], bh[j]);
                }
        }
    }

#pragma unroll
    for (int i = 0; i < 4; i++) {
        int r0 = rowBase + warpM * 64 + i * 16 + (lane >> 2);
#pragma unroll
        for (int rr = 0; rr < 2; rr++) {
            int grow = r0 + rr * 8;
            if (grow >= nrows) continue;
#pragma unroll
            for (int j = 0; j < 4; j++) {
                int gc = colBase + warpN * 32 + j * 8 + (lane & 3) * 2;
                float2 o;
                o.x = acc[i][j][rr * 2 + 0] + bias[gc + 0];
                o.y = acc[i][j][rr * 2 + 1] + bias[gc + 1];
                *reinterpret_cast<float2*>(Cout + (size_t)grow * ldo + gc) = o;
            }
        }
    }
}

// ---------------- split prep ----------------
__global__ void split_a(const float* __restrict__ src, int srcStride, int cols,
                        __nv_bfloat16* __restrict__ hi, __nv_bfloat16* __restrict__ lo)
{
    size_t i = (size_t)blockIdx.x * blockDim.x + threadIdx.x;
    if (i >= (size_t)NN * cols) return;
    int r = (int)(i / cols), c = (int)(i % cols);
    float v = src[(size_t)r * srcStride + c];
    __nv_bfloat16 h = __float2bfloat16_rn(v);
    hi[i] = h;
    lo[i] = __float2bfloat16_rn(v - __bfloat162float(h));
}

// coalesced tiled transpose split: W[K, Mout] -> Bh/Bl[(rowOff+n)*KMAX + k]
__global__ void split_bT(const float* __restrict__ W, const float* __restrict__ b,
                         int K, int Mout, int rowOff,
                         __nv_bfloat16* __restrict__ Bh, __nv_bfloat16* __restrict__ Bl,
                         float* __restrict__ bias)
{
    __shared__ float tile[32][33];
    int nb = blockIdx.x * 32, kb = blockIdx.y * 32;
    int tx = threadIdx.x, ty = threadIdx.y;   // block (32, 8)
#pragma unroll
    for (int i = 0; i < 4; i++) {
        int k = kb + ty + i * 8;
        if (k < K && nb + tx < Mout) tile[ty + i * 8][tx] = W[(size_t)k * Mout + nb + tx];
    }
    __syncthreads();
#pragma unroll
    for (int i = 0; i < 4; i++) {
        int n = nb + ty + i * 8, k = kb + tx;
        if (n < Mout && k < K) {
            float v = tile[tx][ty + i * 8];
            __nv_bfloat16 h = __float2bfloat16_rn(v);
            size_t o = (size_t)(rowOff + n) * KMAX + k;
            Bh[o] = h;
            Bl[o] = __float2bfloat16_rn(v - __bfloat162float(h));
        }
    }
    if (ty == 0 && blockIdx.y == 0 && nb + tx < Mout) bias[rowOff + nb + tx] = b[nb + tx];
}

// ---------------- CSR build ----------------
__global__ void zero_cnt(int* __restrict__ c) {
    int i = blockIdx.x * blockDim.x + threadIdx.x;
    if (i < NN) c[i] = 0;
}
__global__ void hist_dst(const int* __restrict__ ei, int* __restrict__ cnt) {
    int i = blockIdx.x * blockDim.x + threadIdx.x;
    if (i < EE) atomicAdd(&cnt[ei[EE + i]], 1);
}
__global__ void blocksum(const int* __restrict__ cnt, int* __restrict__ bsum) {
    __shared__ int sm[128];
    int idx = blockIdx.x * 128 + threadIdx.x;
    sm[threadIdx.x] = (idx < NN) ? cnt[idx] : 0;
    __syncthreads();
#pragma unroll
    for (int off = 64; off; off >>= 1) {
        if (threadIdx.x < off) sm[threadIdx.x] += sm[threadIdx.x + off];
        __syncthreads();
    }
    if (threadIdx.x == 0) bsum[blockIdx.x] = sm[0];
}
__global__ void scan_bsum(int* __restrict__ bsum, int* __restrict__ rowptr) {
    __shared__ int sm[512];
    int t = threadIdx.x;
    int v = (t < NB) ? bsum[t] : 0;
    sm[t] = v;
    __syncthreads();
#pragma unroll
    for (int off = 1; off < 512; off <<= 1) {
        int x = (t >= off) ? sm[t - off] : 0;
        __syncthreads();
        sm[t] += x;
        __syncthreads();
    }
    if (t < NB) bsum[t] = sm[t] - v;       // exclusive
    if (t == 0) rowptr[NN] = EE;
}
__global__ void write_rowptr(const int* __restrict__ cnt, const int* __restrict__ bsum,
                             int* __restrict__ rowptr, int* __restrict__ cur) {
    __shared__ int sm[128];
    int b = blockIdx.x, t = threadIdx.x;
    int idx = b * 128 + t;
    int v = (idx < NN) ? cnt[idx] : 0;
    sm[t] = v;
    __syncthreads();
#pragma unroll
    for (int off = 1; off < 128; off <<= 1) {
        int x = (t >= off) ? sm[t - off] : 0;
        __syncthreads();
        sm[t] += x;
        __syncthreads();
    }
    if (idx < NN) {
        int r = bsum[b] + sm[t] - v;
        rowptr[idx] = r;
        cur[idx] = r;
    }
}
__global__ void fill_csr(const int* __restrict__ ei, int* __restrict__ cur,
                         int* __restrict__ csrsrc) {
    int i = blockIdx.x * blockDim.x + threadIdx.x;
    if (i >= EE) return;
    int pos = atomicAdd(&cur[ei[EE + i]], 1);
    csrsrc[pos] = ei[i];
}

// ---------------- fused per-node attention ----------------
// block = dst node, warp = head. Pass1: scores + max. Pass2: exp, sum, weighted V.
// mode 0 (layer 1): val = skip + msg; write ELU'd bf16 hi/lo split DIRECTLY to Ah/Al
//                   (feeds layer-2 GEMM; no fp32 write-back, no separate split pass).
// mode 1 (layer 2): mean over heads + skip + ELU -> out[n, outOff + c]
__global__ __launch_bounds__(128) void att_fused(
    const float* __restrict__ qkv, int stride, int qOff, int kOff, int vOff,
    const int* __restrict__ rowptr, const int* __restrict__ csrsrc,
    float* __restrict__ alpha,
    float* __restrict__ outp, int strideOut, int outOff, int mode,
    __nv_bfloat16* __restrict__ Ah, __nv_bfloat16* __restrict__ Al)
{
    int n = blockIdx.x;
    int h = threadIdx.x >> 5, lane = threadIdx.x & 31;
    int r0 = rowptr[n], r1 = rowptr[n + 1];

    const float4 q4 = *reinterpret_cast<const float4*>(
        qkv + (size_t)n * stride + qOff + h * CC + lane * 4);

    float m = -3.0e38f;
    for (int j = r0; j < r1; j++) {
        int src = csrsrc[j];
        float4 k4 = *reinterpret_cast<const float4*>(
            qkv + (size_t)src * stride + kOff + h * CC + lane * 4);
        float d = q4.x * k4.x + q4.y * k4.y + q4.z * k4.z + q4.w * k4.w;
#pragma unroll
        for (int o = 16; o; o >>= 1) d += __shfl_xor_sync(0xFFFFFFFFu, d, o);
        d *= 0.08838834764831845f;     // 1/sqrt(128)
        m = fmaxf(m, d);
        if (lane == 0) alpha[(size_t)j * HH + h] = d;
    }
    __syncwarp();

    float s = 0.f;
    float4 acc = make_float4(0.f, 0.f, 0.f, 0.f);
    for (int j = r0; j < r1; j++) {
        int src = csrsrc[j];
        float e = __expf(alpha[(size_t)j * HH + h] - m);
        s += e;
        float4 v4 = *reinterpret_cast<const float4*>(
            qkv + (size_t)src * stride + vOff + h * CC + lane * 4);
        acc.x += e * v4.x; acc.y += e * v4.y; acc.z += e * v4.z; acc.w += e * v4.w;
    }
    float inv = 1.f / (s + EPS);

    if (mode == 0) {
        const float4 sk = *reinterpret_cast<const float4*>(
            qkv + (size_t)n * stride + outOff + h * CC + lane * 4);
        float v[4];
        v[0] = sk.x + acc.x * inv; v[1] = sk.y + acc.y * inv;
        v[2] = sk.z + acc.z * inv; v[3] = sk.w + acc.w * inv;
        __nv_bfloat16 hb[4], lb[4];
#pragma unroll
        for (int u = 0; u < 4; u++) {
            float e = v[u] > 0.f ? v[u] : expm1f(v[u]);    // ELU fused
            hb[u] = __float2bfloat16_rn(e);
            lb[u] = __float2bfloat16_rn(e - __bfloat162float(hb[u]));
        }
        size_t o = (size_t)n * KMAX + h * CC + lane * 4;
        *reinterpret_cast<uint2*>(Ah + o) = *reinterpret_cast<uint2*>(hb);
        *reinterpret_cast<uint2*>(Al + o) = *reinterpret_cast<uint2*>(lb);
    } else {
        __shared__ float sm[HH][CC];
        float qsc = inv * 0.25f;
        sm[h][lane * 4 + 0] = acc.x * qsc;
        sm[h][lane * 4 + 1] = acc.y * qsc;
        sm[h][lane * 4 + 2] = acc.z * qsc;
        sm[h][lane * 4 + 3] = acc.w * qsc;
        __syncthreads();
        int c = threadIdx.x;
        float val = sm[0][c] + sm[1][c] + sm[2][c] + sm[3][c];
        float* o = outp + (size_t)n * strideOut + outOff + c;
        float r = *o + val;
        *o = r > 0.f ? r : expm1f(r);     // fused ELU (layer 2)
    }
}

// ---------------- pooling + head ----------------
__global__ void zero_pool(float* __restrict__ pool, float* __restrict__ cnt) {
    int i = blockIdx.x * blockDim.x + threadIdx.x;
    if (i < GG * CC) pool[i] = 0.f;
    if (i < GG) cnt[i] = 0.f;
}
__global__ __launch_bounds__(128) void pool_k(
    const float* __restrict__ h, int stride, int off, const int* __restrict__ batch,
    float* __restrict__ pool, float* __restrict__ cnt)
{
    int i = blockIdx.x;
    int g = batch[i];
    int c = threadIdx.x;
    atomicAdd(&pool[(size_t)g * CC + c], h[(size_t)i * stride + off + c]);
    if (c == 0) atomicAdd(&cnt[g], 1.f);
}
__global__ __launch_bounds__(128) void head_k(
    const float* __restrict__ pool, const float* __restrict__ cnt,
    const float* __restrict__ Wfc, const float* __restrict__ bfc,
    float* __restrict__ out)
{
    int g = blockIdx.x, t = threadIdx.x;
    __shared__ float sm[CC];
    __shared__ float logits[NCLS];
    float cv = fmaxf(cnt[g], 1.f);
    sm[t] = pool[(size_t)g * CC + t] / cv;
    __syncthreads();
    if (t < NCLS) {
        float acc = bfc[t];
#pragma unroll 4
        for (int c = 0; c < CC; c++) acc += sm[c] * Wfc[c * NCLS + t];
        logits[t] = acc;
    }
    __syncthreads();
    if (t == 0) {
        float mx = -1e30f;
#pragma unroll
        for (int j = 0; j < NCLS; j++) mx = fmaxf(mx, logits[j]);
        float ssum = 0.f;
#pragma unroll
        for (int j = 0; j < NCLS; j++) ssum += expf(logits[j] - mx);
        float lse = mx + logf(ssum);
#pragma unroll
        for (int j = 0; j < NCLS; j++) out[g * NCLS + j] = logits[j] - lse;
    }
}

// ---------------- launch ----------------
extern "C" void kernel_launch(void* const* d_in, const int* in_sizes, int n_in,
                              void* d_out, int out_size)
{
    const float* x     = (const float*)d_in[0];
    const int*   ei    = (const int*)d_in[1];
    const int*   batch = (const int*)d_in[2];
    const float* Wq1 = (const float*)d_in[3];  const float* bq1 = (const float*)d_in[4];
    const float* Wk1 = (const float*)d_in[5];  const float* bk1 = (const float*)d_in[6];
    const float* Wv1 = (const float*)d_in[7];  const float* bv1 = (const float*)d_in[8];
    const float* Ws1 = (const float*)d_in[9];  const float* bs1 = (const float*)d_in[10];
    const float* Wq2 = (const float*)d_in[11]; const float* bq2 = (const float*)d_in[12];
    const float* Wk2 = (const float*)d_in[13]; const float* bk2 = (const float*)d_in[14];
    const float* Wv2 = (const float*)d_in[15]; const float* bv2 = (const float*)d_in[16];
    const float* Ws2 = (const float*)d_in[17]; const float* bs2 = (const float*)d_in[18];
    const float* Wfc = (const float*)d_in[19]; const float* bfc = (const float*)d_in[20];
    float* out = (float*)d_out;

    float *qkvs1, *qkvs2, *bias, *alpha, *pool, *cntg;
    __nv_bfloat16 *Ah, *Al, *Bh, *Bl;
    int *cnt, *bsum, *rowptr, *cur, *csrsrc;
    cudaGetSymbolAddress((void**)&qkvs1, g_qkvs1);
    cudaGetSymbolAddress((void**)&qkvs2, g_qkvs2);
    cudaGetSymbolAddress((void**)&Ah, g_Ah);
    cudaGetSymbolAddress((void**)&Al, g_Al);
    cudaGetSymbolAddress((void**)&Bh, g_Bh);
    cudaGetSymbolAddress((void**)&Bl, g_Bl);
    cudaGetSymbolAddress((void**)&bias, g_biasv);
    cudaGetSymbolAddress((void**)&alpha, g_alpha);
    cudaGetSymbolAddress((void**)&cnt, g_cnt);
    cudaGetSymbolAddress((void**)&bsum, g_bsum);
    cudaGetSymbolAddress((void**)&rowptr, g_rowptr);
    cudaGetSymbolAddress((void**)&cur, g_cur);
    cudaGetSymbolAddress((void**)&csrsrc, g_csrsrc);
    cudaGetSymbolAddress((void**)&pool, g_pool);
    cudaGetSymbolAddress((void**)&cntg, g_cnt_g);

    cudaFuncSetAttribute(gemm_bf16x3, cudaFuncAttributeMaxDynamicSharedMemorySize, SMEM_GEMM);

    dim3 tb(32, 8);

    // ---------- layer 1 prep (launches 1..5) then GEMM as launch #6 (ncu -s 5) ----------
    split_bT<<<dim3(512 / 32, FF / 32), tb>>>(Wq1, bq1, FF, 512, 0,    Bh, Bl, bias);
    split_bT<<<dim3(512 / 32, FF / 32), tb>>>(Wk1, bk1, FF, 512, 512,  Bh, Bl, bias);
    split_bT<<<dim3(512 / 32, FF / 32), tb>>>(Wv1, bv1, FF, 512, 1024, Bh, Bl, bias);
    split_bT<<<dim3(512 / 32, FF / 32), tb>>>(Ws1, bs1, FF, 512, 1536, Bh, Bl, bias);
    split_a<<<(int)(((size_t)NN * FF + 255) / 256), 256>>>(x, FF, FF, Ah, Al);

    gemm_bf16x3<<<dim3(N1 / 128, NB), 256, SMEM_GEMM>>>(
        Ah, Al, FF, FF, Bh, Bl, bias, qkvs1, N1, NN);

    // ---------- CSR build (once, reused by both layers) ----------
    zero_cnt<<<(NN + 255) / 256, 256>>>(cnt);
    hist_dst<<<(EE + 255) / 256, 256>>>(ei, cnt);
    blocksum<<<NB, 128>>>(cnt, bsum);
    scan_bsum<<<1, 512>>>(bsum, rowptr);
    write_rowptr<<<NB, 128>>>(cnt, bsum, rowptr, cur);
    fill_csr<<<(EE + 255) / 256, 256>>>(ei, cur, csrsrc);

    // ---------- layer 1 attention (writes layer-2 GEMM input bf16 split directly) ----------
    att_fused<<<NN, 128>>>(qkvs1, N1, 0, 512, 1024, rowptr, csrsrc, alpha,
                           nullptr, 0, 1536, 0, Ah, Al);

    // ---------- layer 2 prep ----------
    split_bT<<<dim3(512 / 32, 512 / 32), tb>>>(Wq2, bq2, 512, 512, 0,    Bh, Bl, bias);
    split_bT<<<dim3(512 / 32, 512 / 32), tb>>>(Wk2, bk2, 512, 512, 512,  Bh, Bl, bias);
    split_bT<<<dim3(512 / 32, 512 / 32), tb>>>(Wv2, bv2, 512, 512, 1024, Bh, Bl, bias);
    split_bT<<<dim3(128 / 32, 512 / 32), tb>>>(Ws2, bs2, 512, 128, 1536, Bh, Bl, bias);

    // ---------- layer 2 fused GEMM + attention (mean + skip + ELU fused) ----------
    gemm_bf16x3<<<dim3(N2 / 128, NB), 256, SMEM_GEMM>>>(
        Ah, Al, 512, 512, Bh, Bl, bias, qkvs2, N2, NN);
    att_fused<<<NN, 128>>>(qkvs2, N2, 0, 512, 1024, rowptr, csrsrc, alpha,
                           qkvs2, N2, 1536, 1, nullptr, nullptr);

    // ---------- pooling + classifier ----------
    zero_pool<<<(GG * CC + 255) / 256, 256>>>(pool, cntg);
    pool_k<<<NN, 128>>>(qkvs2, N2, 1536, batch, pool, cntg);
    head_k<<<GG, 128>>>(pool, cntg, Wfc, bfc, out);
}

// round 6
// speedup vs baseline: 3.2309x; 1.2022x over previous
#include <cuda_runtime.h>
#include <cuda_fp16.h>
#include <cstdint>
#include <cstddef>

// ---------------- problem dims ----------------
#define NN 50000
#define FF 256
#define EE 200000
#define HH 4
#define CC 128
#define GG 256
#define NCLS 10
#define EPS 1e-16f

#define N1 2048            // layer1 fused output cols: q|k|v|skip (4*512)
#define N2 1664            // layer2 fused output cols: q|k|v (3*512) | skip (128)
#define KMAX 512
#define NB 391             // ceil(NN/128)

// ---------------- scratch (device globals) ----------------
__device__ __align__(256) float  g_qkvs1[(size_t)NN * N1];
__device__ __align__(256) float  g_qkvs2[(size_t)NN * N2];
__device__ __align__(256) __half g_Ah[(size_t)NN * KMAX];
__device__ __align__(256) __half g_Al[(size_t)NN * KMAX];
__device__ __align__(256) __half g_Bh[(size_t)N1 * KMAX];
__device__ __align__(256) float  g_biasv[N1];
__device__ __align__(256) float  g_alpha[(size_t)EE * HH];
__device__ __align__(256) int    g_cnt[NN];
__device__ __align__(256) int    g_bsum[512];
__device__ __align__(256) int    g_rowptr[NN + 1];
__device__ __align__(256) int    g_cur[NN];
__device__ __align__(256) int    g_csrsrc[EE];
__device__ __align__(256) float  g_pool[GG * CC];
__device__ __align__(256) float  g_cnt_g[GG];

// ---------------- PTX helpers (sm_80-generic) ----------------
__device__ __forceinline__ uint32_t smem_u32(const void* p) {
    uint32_t a;
    asm("{ .reg .u64 t; cvta.to.shared.u64 t, %1; cvt.u32.u64 %0, t; }" : "=r"(a) : "l"(p));
    return a;
}
__device__ __forceinline__ void cp16(uint32_t dst, const void* src, unsigned srcsz) {
    asm volatile("cp.async.cg.shared.global [%0], [%1], 16, %2;"
                 :: "r"(dst), "l"(src), "r"(srcsz) : "memory");
}
__device__ __forceinline__ void ldsm4(uint32_t& r0, uint32_t& r1, uint32_t& r2, uint32_t& r3,
                                      uint32_t a) {
    asm volatile("ldmatrix.sync.aligned.m8n8.x4.shared.b16 {%0,%1,%2,%3}, [%4];"
                 : "=r"(r0), "=r"(r1), "=r"(r2), "=r"(r3) : "r"(a));
}
__device__ __forceinline__ void mma_f16(float* c, const uint32_t* a, const uint32_t* b) {
    asm volatile(
        "mma.sync.aligned.m16n8k16.row.col.f32.f16.f16.f32 "
        "{%0,%1,%2,%3}, {%4,%5,%6,%7}, {%8,%9}, {%0,%1,%2,%3};"
        : "+f"(c[0]), "+f"(c[1]), "+f"(c[2]), "+f"(c[3])
        : "r"(a[0]), "r"(a[1]), "r"(a[2]), "r"(a[3]), "r"(b[0]), "r"(b[1]));
}

// ---------------- fp16x2 tensor-core GEMM (2 MMA passes, 4-stage cp.async) ----
// C = (Ah + Al) @ B^T + bias.   A split fp16 hi/lo (err 2^-22), B single fp16.
#define TILE_B   (128 * 80)               // 10240 B per 128x32 fp16 tile (80B row pad)
#define STAGE_B  (3 * TILE_B)             // Ah, Al, B = 30720 B per stage
#define SMEM_GEMM (4 * STAGE_B)           // 122880 B

__global__ __launch_bounds__(256, 1)
void gemm_f16x2(const __half* __restrict__ Ahb, const __half* __restrict__ Alb,
                int lda, int K,
                const __half* __restrict__ Bhb,
                const float* __restrict__ bias, float* __restrict__ Cout, int ldo, int nrows)
{
    extern __shared__ char smem[];
    const uint32_t sb = smem_u32(smem);
    const int tid = threadIdx.x;
    const int lane = tid & 31;
    const int wid = tid >> 5;
    const int warpM = wid & 1;
    const int warpN = wid >> 1;
    const int rowBase = blockIdx.y * 128;
    const int colBase = blockIdx.x * 128;

    float acc[4][4][4];
#pragma unroll
    for (int i = 0; i < 4; i++)
#pragma unroll
        for (int j = 0; j < 4; j++)
#pragma unroll
            for (int f = 0; f < 4; f++) acc[i][j][f] = 0.f;

    const int T = K >> 5;

    auto loadStage = [&](int s, int k0) {
        uint32_t base = sb + s * STAGE_B;
#pragma unroll
        for (int t = 0; t < 2; t++) {
            int c = tid + t * 256;
            int r = c >> 2;
            int q = c & 3;
            uint32_t soff = (uint32_t)(r * 80 + q * 16);
            int ga = rowBase + r;
            unsigned va = (ga < nrows) ? 16u : 0u;
            int gac = (ga < nrows) ? ga : (nrows - 1);
            size_t aoff = (size_t)gac * lda + k0 + q * 8;
            cp16(base + soff,              Ahb + aoff, va);
            cp16(base + TILE_B + soff,     Alb + aoff, va);
            size_t boff = (size_t)(colBase + r) * KMAX + k0 + q * 8;
            cp16(base + 2 * TILE_B + soff, Bhb + boff, 16u);
        }
        asm volatile("cp.async.commit_group;" ::: "memory");
    };

    const uint32_t aOff = (uint32_t)((warpM * 64 + (lane & 15)) * 80 + (lane >> 4) * 16);
    const uint32_t bOff = (uint32_t)((warpN * 32 + (lane & 7) + ((lane >> 4) & 1) * 8) * 80
                                     + ((lane >> 3) & 1) * 16);

    loadStage(0, 0);
    loadStage(1, 32);

    for (int it = 0; it < T; it++) {
        if (it + 2 < T) loadStage((it + 2) & 3, (it + 2) << 5);
        int pend = ((it + 2 < T) ? 2 : (it + 1 < T) ? 1 : 0);
        if (pend == 2)      asm volatile("cp.async.wait_group 2;" ::: "memory");
        else if (pend == 1) asm volatile("cp.async.wait_group 1;" ::: "memory");
        else                asm volatile("cp.async.wait_group 0;" ::: "memory");
        __syncthreads();   // single barrier also guards stage rewrite (depth 2 < 4 stages)

        uint32_t tb = sb + (it & 3) * STAGE_B;
#pragma unroll
        for (int ks = 0; ks < 2; ks++) {
            uint32_t kb = ks * 32;
            uint32_t ah[4][4], al[4][4];
#pragma unroll
            for (int i = 0; i < 4; i++) {
                uint32_t ad = tb + aOff + i * (16 * 80) + kb;
                ldsm4(ah[i][0], ah[i][1], ah[i][2], ah[i][3], ad);
                ldsm4(al[i][0], al[i][1], al[i][2], al[i][3], ad + TILE_B);
            }
            uint32_t bb[4][2];
#pragma unroll
            for (int j2 = 0; j2 < 2; j2++) {
                uint32_t bd = tb + 2 * TILE_B + bOff + j2 * (16 * 80) + kb;
                uint32_t t0, t1, t2, t3;
                ldsm4(t0, t1, t2, t3, bd);
                bb[j2 * 2][0] = t0; bb[j2 * 2][1] = t1;
                bb[j2 * 2 + 1][0] = t2; bb[j2 * 2 + 1][1] = t3;
            }
#pragma unroll
            for (int i = 0; i < 4; i++)
#pragma unroll
                for (int j = 0; j < 4; j++) {
                    mma_f16(acc[i][j], ah[i], bb[j]);
                    mma_f16(acc[i][j], al[i], bb[j]);
                }
        }
    }

#pragma unroll
    for (int i = 0; i < 4; i++) {
        int r0 = rowBase + warpM * 64 + i * 16 + (lane >> 2);
#pragma unroll
        for (int rr = 0; rr < 2; rr++) {
            int grow = r0 + rr * 8;
            if (grow >= nrows) continue;
#pragma unroll
            for (int j = 0; j < 4; j++) {
                int gc = colBase + warpN * 32 + j * 8 + (lane & 3) * 2;
                float2 o;
                o.x = acc[i][j][rr * 2 + 0] + bias[gc + 0];
                o.y = acc[i][j][rr * 2 + 1] + bias[gc + 1];
                *reinterpret_cast<float2*>(Cout + (size_t)grow * ldo + gc) = o;
            }
        }
    }
}

// ---------------- split prep ----------------
__global__ void split_a(const float* __restrict__ src, int srcStride, int cols,
                        __half* __restrict__ hi, __half* __restrict__ lo)
{
    size_t i = (size_t)blockIdx.x * blockDim.x + threadIdx.x;
    if (i >= (size_t)NN * cols) return;
    int r = (int)(i / cols), c = (int)(i % cols);
    float v = src[(size_t)r * srcStride + c];
    __half h = __float2half_rn(v);
    hi[i] = h;
    lo[i] = __float2half_rn(v - __half2float(h));
}

// coalesced tiled transpose: W[K, Mout] -> B[(rowOff+n)*KMAX + k] (single fp16)
__global__ void split_bT(const float* __restrict__ W, const float* __restrict__ b,
                         int K, int Mout, int rowOff,
                         __half* __restrict__ Bh, float* __restrict__ bias)
{
    __shared__ float tile[32][33];
    int nb = blockIdx.x * 32, kb = blockIdx.y * 32;
    int tx = threadIdx.x, ty = threadIdx.y;   // block (32, 8)
#pragma unroll
    for (int i = 0; i < 4; i++) {
        int k = kb + ty + i * 8;
        if (k < K && nb + tx < Mout) tile[ty + i * 8][tx] = W[(size_t)k * Mout + nb + tx];
    }
    __syncthreads();
#pragma unroll
    for (int i = 0; i < 4; i++) {
        int n = nb + ty + i * 8, k = kb + tx;
        if (n < Mout && k < K)
            Bh[(size_t)(rowOff + n) * KMAX + k] = __float2half_rn(tile[tx][ty + i * 8]);
    }
    if (ty == 0 && blockIdx.y == 0 && nb + tx < Mout) bias[rowOff + nb + tx] = b[nb + tx];
}

// ---------------- CSR build ----------------
__global__ void zero_cnt(int* __restrict__ c) {
    int i = blockIdx.x * blockDim.x + threadIdx.x;
    if (i < NN) c[i] = 0;
}
__global__ void hist_dst(const int* __restrict__ ei, int* __restrict__ cnt) {
    int i = blockIdx.x * blockDim.x + threadIdx.x;
    if (i < EE) atomicAdd(&cnt[ei[EE + i]], 1);
}
__global__ void blocksum(const int* __restrict__ cnt, int* __restrict__ bsum) {
    __shared__ int sm[128];
    int idx = blockIdx.x * 128 + threadIdx.x;
    sm[threadIdx.x] = (idx < NN) ? cnt[idx] : 0;
    __syncthreads();
#pragma unroll
    for (int off = 64; off; off >>= 1) {
        if (threadIdx.x < off) sm[threadIdx.x] += sm[threadIdx.x + off];
        __syncthreads();
    }
    if (threadIdx.x == 0) bsum[blockIdx.x] = sm[0];
}
__global__ void scan_bsum(int* __restrict__ bsum, int* __restrict__ rowptr) {
    __shared__ int sm[512];
    int t = threadIdx.x;
    int v = (t < NB) ? bsum[t] : 0;
    sm[t] = v;
    __syncthreads();
#pragma unroll
    for (int off = 1; off < 512; off <<= 1) {
        int x = (t >= off) ? sm[t - off] : 0;
        __syncthreads();
        sm[t] += x;
        __syncthreads();
    }
    if (t < NB) bsum[t] = sm[t] - v;       // exclusive
    if (t == 0) rowptr[NN] = EE;
}
__global__ void write_rowptr(const int* __restrict__ cnt, const int* __restrict__ bsum,
                             int* __restrict__ rowptr, int* __restrict__ cur) {
    __shared__ int sm[128];
    int b = blockIdx.x, t = threadIdx.x;
    int idx = b * 128 + t;
    int v = (idx < NN) ? cnt[idx] : 0;
    sm[t] = v;
    __syncthreads();
#pragma unroll
    for (int off = 1; off < 128; off <<= 1) {
        int x = (t >= off) ? sm[t - off] : 0;
        __syncthreads();
        sm[t] += x;
        __syncthreads();
    }
    if (idx < NN) {
        int r = bsum[b] + sm[t] - v;
        rowptr[idx] = r;
        cur[idx] = r;
    }
}
__global__ void fill_csr(const int* __restrict__ ei, int* __restrict__ cur,
                         int* __restrict__ csrsrc) {
    int i = blockIdx.x * blockDim.x + threadIdx.x;
    if (i >= EE) return;
    int pos = atomicAdd(&cur[ei[EE + i]], 1);
    csrsrc[pos] = ei[i];
}

// ---------------- fused per-node attention ----------------
// block = dst node, warp = head. Pass1: scores + max. Pass2: exp, sum, weighted V.
// mode 0 (layer 1): val = skip + msg, ELU'd, written as fp16 hi/lo to Ah/Al
//                   (direct layer-2 GEMM input; no fp32 write-back).
// mode 1 (layer 2): mean over heads + skip + ELU -> out[n, outOff + c]
__global__ __launch_bounds__(128) void att_fused(
    const float* __restrict__ qkv, int stride, int qOff, int kOff, int vOff,
    const int* __restrict__ rowptr, const int* __restrict__ csrsrc,
    float* __restrict__ alpha,
    float* __restrict__ outp, int strideOut, int outOff, int mode,
    __half* __restrict__ Ah, __half* __restrict__ Al)
{
    int n = blockIdx.x;
    int h = threadIdx.x >> 5, lane = threadIdx.x & 31;
    int r0 = rowptr[n], r1 = rowptr[n + 1];

    const float4 q4 = *reinterpret_cast<const float4*>(
        qkv + (size_t)n * stride + qOff + h * CC + lane * 4);

    float m = -3.0e38f;
    for (int j = r0; j < r1; j++) {
        int src = csrsrc[j];
        float4 k4 = *reinterpret_cast<const float4*>(
            qkv + (size_t)src * stride + kOff + h * CC + lane * 4);
        float d = q4.x * k4.x + q4.y * k4.y + q4.z * k4.z + q4.w * k4.w;
#pragma unroll
        for (int o = 16; o; o >>= 1) d += __shfl_xor_sync(0xFFFFFFFFu, d, o);
        d *= 0.08838834764831845f;     // 1/sqrt(128)
        m = fmaxf(m, d);
        if (lane == 0) alpha[(size_t)j * HH + h] = d;
    }
    __syncwarp();

    float s = 0.f;
    float4 acc = make_float4(0.f, 0.f, 0.f, 0.f);
    for (int j = r0; j < r1; j++) {
        int src = csrsrc[j];
        float e = __expf(alpha[(size_t)j * HH + h] - m);
        s += e;
        float4 v4 = *reinterpret_cast<const float4*>(
            qkv + (size_t)src * stride + vOff + h * CC + lane * 4);
        acc.x += e * v4.x; acc.y += e * v4.y; acc.z += e * v4.z; acc.w += e * v4.w;
    }
    float inv = 1.f / (s + EPS);

    if (mode == 0) {
        const float4 sk = *reinterpret_cast<const float4*>(
            qkv + (size_t)n * stride + outOff + h * CC + lane * 4);
        float v[4];
        v[0] = sk.x + acc.x * inv; v[1] = sk.y + acc.y * inv;
        v[2] = sk.z + acc.z * inv; v[3] = sk.w + acc.w * inv;
        __half hb[4], lb[4];
#pragma unroll
        for (int u = 0; u < 4; u++) {
            float e = v[u] > 0.f ? v[u] : expm1f(v[u]);    // ELU fused
            hb[u] = __float2half_rn(e);
            lb[u] = __float2half_rn(e - __half2float(hb[u]));
        }
        size_t o = (size_t)n * KMAX + h * CC + lane * 4;
        *reinterpret_cast<uint2*>(Ah + o) = *reinterpret_cast<uint2*>(hb);
        *reinterpret_cast<uint2*>(Al + o) = *reinterpret_cast<uint2*>(lb);
    } else {
        __shared__ float sm[HH][CC];
        float qsc = inv * 0.25f;
        sm[h][lane * 4 + 0] = acc.x * qsc;
        sm[h][lane * 4 + 1] = acc.y * qsc;
        sm[h][lane * 4 + 2] = acc.z * qsc;
        sm[h][lane * 4 + 3] = acc.w * qsc;
        __syncthreads();
        int c = threadIdx.x;
        float val = sm[0][c] + sm[1][c] + sm[2][c] + sm[3][c];
        float* o = outp + (size_t)n * strideOut + outOff + c;
        float r = *o + val;
        *o = r > 0.f ? r : expm1f(r);     // fused ELU (layer 2)
    }
}

// ---------------- pooling + head ----------------
__global__ void zero_pool(float* __restrict__ pool, float* __restrict__ cnt) {
    int i = blockIdx.x * blockDim.x + threadIdx.x;
    if (i < GG * CC) pool[i] = 0.f;
    if (i < GG) cnt[i] = 0.f;
}
__global__ __launch_bounds__(128) void pool_k(
    const float* __restrict__ h, int stride, int off, const int* __restrict__ batch,
    float* __restrict__ pool, float* __restrict__ cnt)
{
    int i = blockIdx.x;
    int g = batch[i];
    int c = threadIdx.x;
    atomicAdd(&pool[(size_t)g * CC + c], h[(size_t)i * stride + off + c]);
    if (c == 0) atomicAdd(&cnt[g], 1.f);
}
__global__ __launch_bounds__(128) void head_k(
    const float* __restrict__ pool, const float* __restrict__ cnt,
    const float* __restrict__ Wfc, const float* __restrict__ bfc,
    float* __restrict__ out)
{
    int g = blockIdx.x, t = threadIdx.x;
    __shared__ float sm[CC];
    __shared__ float logits[NCLS];
    float cv = fmaxf(cnt[g], 1.f);
    sm[t] = pool[(size_t)g * CC + t] / cv;
    __syncthreads();
    if (t < NCLS) {
        float acc = bfc[t];
#pragma unroll 4
        for (int c = 0; c < CC; c++) acc += sm[c] * Wfc[c * NCLS + t];
        logits[t] = acc;
    }
    __syncthreads();
    if (t == 0) {
        float mx = -1e30f;
#pragma unroll
        for (int j = 0; j < NCLS; j++) mx = fmaxf(mx, logits[j]);
        float ssum = 0.f;
#pragma unroll
        for (int j = 0; j < NCLS; j++) ssum += expf(logits[j] - mx);
        float lse = mx + logf(ssum);
#pragma unroll
        for (int j = 0; j < NCLS; j++) out[g * NCLS + j] = logits[j] - lse;
    }
}

// ---------------- launch ----------------
extern "C" void kernel_launch(void* const* d_in, const int* in_sizes, int n_in,
                              void* d_out, int out_size)
{
    const float* x     = (const float*)d_in[0];
    const int*   ei    = (const int*)d_in[1];
    const int*   batch = (const int*)d_in[2];
    const float* Wq1 = (const float*)d_in[3];  const float* bq1 = (const float*)d_in[4];
    const float* Wk1 = (const float*)d_in[5];  const float* bk1 = (const float*)d_in[6];
    const float* Wv1 = (const float*)d_in[7];  const float* bv1 = (const float*)d_in[8];
    const float* Ws1 = (const float*)d_in[9];  const float* bs1 = (const float*)d_in[10];
    const float* Wq2 = (const float*)d_in[11]; const float* bq2 = (const float*)d_in[12];
    const float* Wk2 = (const float*)d_in[13]; const float* bk2 = (const float*)d_in[14];
    const float* Wv2 = (const float*)d_in[15]; const float* bv2 = (const float*)d_in[16];
    const float* Ws2 = (const float*)d_in[17]; const float* bs2 = (const float*)d_in[18];
    const float* Wfc = (const float*)d_in[19]; const float* bfc = (const float*)d_in[20];
    float* out = (float*)d_out;

    float *qkvs1, *qkvs2, *bias, *alpha, *pool, *cntg;
    __half *Ah, *Al, *Bh;
    int *cnt, *bsum, *rowptr, *cur, *csrsrc;
    cudaGetSymbolAddress((void**)&qkvs1, g_qkvs1);
    cudaGetSymbolAddress((void**)&qkvs2, g_qkvs2);
    cudaGetSymbolAddress((void**)&Ah, g_Ah);
    cudaGetSymbolAddress((void**)&Al, g_Al);
    cudaGetSymbolAddress((void**)&Bh, g_Bh);
    cudaGetSymbolAddress((void**)&bias, g_biasv);
    cudaGetSymbolAddress((void**)&alpha, g_alpha);
    cudaGetSymbolAddress((void**)&cnt, g_cnt);
    cudaGetSymbolAddress((void**)&bsum, g_bsum);
    cudaGetSymbolAddress((void**)&rowptr, g_rowptr);
    cudaGetSymbolAddress((void**)&cur, g_cur);
    cudaGetSymbolAddress((void**)&csrsrc, g_csrsrc);
    cudaGetSymbolAddress((void**)&pool, g_pool);
    cudaGetSymbolAddress((void**)&cntg, g_cnt_g);

    cudaFuncSetAttribute(gemm_f16x2, cudaFuncAttributeMaxDynamicSharedMemorySize, SMEM_GEMM);

    dim3 tb(32, 8);

    // ---------- layer 1 prep, then GEMM ----------
    split_bT<<<dim3(512 / 32, FF / 32), tb>>>(Wq1, bq1, FF, 512, 0,    Bh, bias);
    split_bT<<<dim3(512 / 32, FF / 32), tb>>>(Wk1, bk1, FF, 512, 512,  Bh, bias);
    split_bT<<<dim3(512 / 32, FF / 32), tb>>>(Wv1, bv1, FF, 512, 1024, Bh, bias);
    split_bT<<<dim3(512 / 32, FF / 32), tb>>>(Ws1, bs1, FF, 512, 1536, Bh, bias);
    split_a<<<(int)(((size_t)NN * FF + 255) / 256), 256>>>(x, FF, FF, Ah, Al);

    gemm_f16x2<<<dim3(N1 / 128, NB), 256, SMEM_GEMM>>>(
        Ah, Al, FF, FF, Bh, bias, qkvs1, N1, NN);

    // ---------- CSR build (once, reused by both layers) ----------
    zero_cnt<<<(NN + 255) / 256, 256>>>(cnt);
    hist_dst<<<(EE + 255) / 256, 256>>>(ei, cnt);
    blocksum<<<NB, 128>>>(cnt, bsum);
    scan_bsum<<<1, 512>>>(bsum, rowptr);
    write_rowptr<<<NB, 128>>>(cnt, bsum, rowptr, cur);
    fill_csr<<<(EE + 255) / 256, 256>>>(ei, cur, csrsrc);

    // ---------- layer 1 attention (emits layer-2 GEMM fp16 input directly) ----------
    att_fused<<<NN, 128>>>(qkvs1, N1, 0, 512, 1024, rowptr, csrsrc, alpha,
                           nullptr, 0, 1536, 0, Ah, Al);

    // ---------- layer 2 prep ----------
    split_bT<<<dim3(512 / 32, 512 / 32), tb>>>(Wq2, bq2, 512, 512, 0,    Bh, bias);
    split_bT<<<dim3(512 / 32, 512 / 32), tb>>>(Wk2, bk2, 512, 512, 512,  Bh, bias);
    split_bT<<<dim3(512 / 32, 512 / 32), tb>>>(Wv2, bv2, 512, 512, 1024, Bh, bias);
    split_bT<<<dim3(128 / 32, 512 / 32), tb>>>(Ws2, bs2, 512, 128, 1536, Bh, bias);

    // ---------- layer 2 fused GEMM + attention (mean + skip + ELU fused) ----------
    gemm_f16x2<<<dim3(N2 / 128, NB), 256, SMEM_GEMM>>>(
        Ah, Al, 512, 512, Bh, bias, qkvs2, N2, NN);
    att_fused<<<NN, 128>>>(qkvs2, N2, 0, 512, 1024, rowptr, csrsrc, alpha,
                           qkvs2, N2, 1536, 1, nullptr, nullptr);

    // ---------- pooling + classifier ----------
    zero_pool<<<(GG * CC + 255) / 256, 256>>>(pool, cntg);
    pool_k<<<NN, 128>>>(qkvs2, N2, 1536, batch, pool, cntg);
    head_k<<<GG, 128>>>(pool, cntg, Wfc, bfc, out);
}

// round 7
// speedup vs baseline: 4.9305x; 1.5260x over previous
#include <cuda_runtime.h>
#include <cuda_fp16.h>
#include <cstdint>
#include <cstddef>

// ---------------- problem dims ----------------
#define NN 50000
#define FF 256
#define EE 200000
#define HH 4
#define CC 128
#define GG 256
#define NCLS 10
#define EPS 1e-16f

#define N1 2048            // layer1 fused output cols: q|k|v|skip (4*512)
#define N2 1664            // layer2 fused output cols: q|k|v (3*512) | skip (128)
#define KMAX 512
#define NB 391             // ceil(NN/128)

// ---------------- scratch (device globals) ----------------
__device__ __align__(256) __half g_qkvs1[(size_t)NN * N1];
__device__ __align__(256) __half g_qkvs2[(size_t)NN * N2];
__device__ __align__(256) __half g_A[(size_t)NN * KMAX];
__device__ __align__(256) __half g_B[(size_t)N1 * KMAX];
__device__ __align__(256) float  g_h2[(size_t)NN * CC];
__device__ __align__(256) float  g_biasv[N1];
__device__ __align__(256) float  g_alpha[(size_t)EE * HH];
__device__ __align__(256) int    g_cnt[NN];
__device__ __align__(256) int    g_bsum[512];
__device__ __align__(256) int    g_rowptr[NN + 1];
__device__ __align__(256) int    g_cur[NN];
__device__ __align__(256) int    g_csrsrc[EE];
__device__ __align__(256) float  g_pool[GG * CC];
__device__ __align__(256) float  g_cnt_g[GG];

// ---------------- PTX helpers (sm_80-generic) ----------------
__device__ __forceinline__ uint32_t smem_u32(const void* p) {
    uint32_t a;
    asm("{ .reg .u64 t; cvta.to.shared.u64 t, %1; cvt.u32.u64 %0, t; }" : "=r"(a) : "l"(p));
    return a;
}
__device__ __forceinline__ void cp16(uint32_t dst, const void* src, unsigned srcsz) {
    asm volatile("cp.async.cg.shared.global [%0], [%1], 16, %2;"
                 :: "r"(dst), "l"(src), "r"(srcsz) : "memory");
}
__device__ __forceinline__ void ldsm4(uint32_t& r0, uint32_t& r1, uint32_t& r2, uint32_t& r3,
                                      uint32_t a) {
    asm volatile("ldmatrix.sync.aligned.m8n8.x4.shared.b16 {%0,%1,%2,%3}, [%4];"
                 : "=r"(r0), "=r"(r1), "=r"(r2), "=r"(r3) : "r"(a));
}
__device__ __forceinline__ void mma_f16(float* c, const uint32_t* a, const uint32_t* b) {
    asm volatile(
        "mma.sync.aligned.m16n8k16.row.col.f32.f16.f16.f32 "
        "{%0,%1,%2,%3}, {%4,%5,%6,%7}, {%8,%9}, {%0,%1,%2,%3};"
        : "+f"(c[0]), "+f"(c[1]), "+f"(c[2]), "+f"(c[3])
        : "r"(a[0]), "r"(a[1]), "r"(a[2]), "r"(a[3]), "r"(b[0]), "r"(b[1]));
}

// ---------------- fp16 tensor-core GEMM (1 MMA pass, 4-stage cp.async) ------
// C = A @ B^T + bias, fp32 accum, fp16 output.
#define TILE_B   (128 * 80)               // 10240 B per 128x32 fp16 tile (80B row pad)
#define STAGE_B  (2 * TILE_B)             // A, B = 20480 B per stage
#define SMEM_GEMM (4 * STAGE_B)           // 81920 B -> 2 CTAs/SM

__global__ __launch_bounds__(256)
void gemm_f16(const __half* __restrict__ Ab, int lda, int K,
              const __half* __restrict__ Bb,
              const float* __restrict__ bias, __half* __restrict__ Cout, int ldo, int nrows)
{
    extern __shared__ char smem[];
    const uint32_t sb = smem_u32(smem);
    const int tid = threadIdx.x;
    const int lane = tid & 31;
    const int wid = tid >> 5;
    const int warpM = wid & 1;
    const int warpN = wid >> 1;
    const int rowBase = blockIdx.y * 128;
    const int colBase = blockIdx.x * 128;

    float acc[4][4][4];
#pragma unroll
    for (int i = 0; i < 4; i++)
#pragma unroll
        for (int j = 0; j < 4; j++)
#pragma unroll
            for (int f = 0; f < 4; f++) acc[i][j][f] = 0.f;

    const int T = K >> 5;

    auto loadStage = [&](int s, int k0) {
        uint32_t base = sb + s * STAGE_B;
#pragma unroll
        for (int t = 0; t < 2; t++) {
            int c = tid + t * 256;
            int r = c >> 2;
            int q = c & 3;
            uint32_t soff = (uint32_t)(r * 80 + q * 16);
            int ga = rowBase + r;
            unsigned va = (ga < nrows) ? 16u : 0u;
            int gac = (ga < nrows) ? ga : (nrows - 1);
            cp16(base + soff,          Ab + (size_t)gac * lda + k0 + q * 8, va);
            cp16(base + TILE_B + soff, Bb + (size_t)(colBase + r) * KMAX + k0 + q * 8, 16u);
        }
        asm volatile("cp.async.commit_group;" ::: "memory");
    };

    const uint32_t aOff = (uint32_t)((warpM * 64 + (lane & 15)) * 80 + (lane >> 4) * 16);
    const uint32_t bOff = (uint32_t)((warpN * 32 + (lane & 7) + ((lane >> 4) & 1) * 8) * 80
                                     + ((lane >> 3) & 1) * 16);

    loadStage(0, 0);
    loadStage(1, 32);

    for (int it = 0; it < T; it++) {
        if (it + 2 < T) loadStage((it + 2) & 3, (it + 2) << 5);
        int pend = ((it + 2 < T) ? 2 : (it + 1 < T) ? 1 : 0);
        if (pend == 2)      asm volatile("cp.async.wait_group 2;" ::: "memory");
        else if (pend == 1) asm volatile("cp.async.wait_group 1;" ::: "memory");
        else                asm volatile("cp.async.wait_group 0;" ::: "memory");
        __syncthreads();

        uint32_t tb = sb + (it & 3) * STAGE_B;
#pragma unroll
        for (int ks = 0; ks < 2; ks++) {
            uint32_t kb = ks * 32;
            uint32_t ah[4][4];
#pragma unroll
            for (int i = 0; i < 4; i++) {
                uint32_t ad = tb + aOff + i * (16 * 80) + kb;
                ldsm4(ah[i][0], ah[i][1], ah[i][2], ah[i][3], ad);
            }
            uint32_t bb[4][2];
#pragma unroll
            for (int j2 = 0; j2 < 2; j2++) {
                uint32_t bd = tb + TILE_B + bOff + j2 * (16 * 80) + kb;
                uint32_t t0, t1, t2, t3;
                ldsm4(t0, t1, t2, t3, bd);
                bb[j2 * 2][0] = t0; bb[j2 * 2][1] = t1;
                bb[j2 * 2 + 1][0] = t2; bb[j2 * 2 + 1][1] = t3;
            }
#pragma unroll
            for (int i = 0; i < 4; i++)
#pragma unroll
                for (int j = 0; j < 4; j++)
                    mma_f16(acc[i][j], ah[i], bb[j]);
        }
    }

#pragma unroll
    for (int i = 0; i < 4; i++) {
        int r0 = rowBase + warpM * 64 + i * 16 + (lane >> 2);
#pragma unroll
        for (int rr = 0; rr < 2; rr++) {
            int grow = r0 + rr * 8;
            if (grow >= nrows) continue;
#pragma unroll
            for (int j = 0; j < 4; j++) {
                int gc = colBase + warpN * 32 + j * 8 + (lane & 3) * 2;
                __half2 o = __floats2half2_rn(acc[i][j][rr * 2 + 0] + bias[gc + 0],
                                              acc[i][j][rr * 2 + 1] + bias[gc + 1]);
                *reinterpret_cast<__half2*>(Cout + (size_t)grow * ldo + gc) = o;
            }
        }
    }
}

// ---------------- prep kernels ----------------
__global__ void cvt_a(const float* __restrict__ src, int cols, __half* __restrict__ dst)
{
    size_t i = (size_t)blockIdx.x * blockDim.x + threadIdx.x;
    if (i < (size_t)NN * cols) dst[i] = __float2half_rn(src[i]);
}

// coalesced tiled transpose: W[K, Mout] -> B[(rowOff+n)*KMAX + k] (fp16)
__global__ void split_bT(const float* __restrict__ W, const float* __restrict__ b,
                         int K, int Mout, int rowOff,
                         __half* __restrict__ Bh, float* __restrict__ bias)
{
    __shared__ float tile[32][33];
    int nb = blockIdx.x * 32, kb = blockIdx.y * 32;
    int tx = threadIdx.x, ty = threadIdx.y;   // block (32, 8)
#pragma unroll
    for (int i = 0; i < 4; i++) {
        int k = kb + ty + i * 8;
        if (k < K && nb + tx < Mout) tile[ty + i * 8][tx] = W[(size_t)k * Mout + nb + tx];
    }
    __syncthreads();
#pragma unroll
    for (int i = 0; i < 4; i++) {
        int n = nb + ty + i * 8, k = kb + tx;
        if (n < Mout && k < K)
            Bh[(size_t)(rowOff + n) * KMAX + k] = __float2half_rn(tile[tx][ty + i * 8]);
    }
    if (ty == 0 && blockIdx.y == 0 && nb + tx < Mout) bias[rowOff + nb + tx] = b[nb + tx];
}

// ---------------- CSR build ----------------
__global__ void zero_cnt(int* __restrict__ c) {
    int i = blockIdx.x * blockDim.x + threadIdx.x;
    if (i < NN) c[i] = 0;
}
__global__ void hist_dst(const int* __restrict__ ei, int* __restrict__ cnt) {
    int i = blockIdx.x * blockDim.x + threadIdx.x;
    if (i < EE) atomicAdd(&cnt[ei[EE + i]], 1);
}
__global__ void blocksum(const int* __restrict__ cnt, int* __restrict__ bsum) {
    __shared__ int sm[128];
    int idx = blockIdx.x * 128 + threadIdx.x;
    sm[threadIdx.x] = (idx < NN) ? cnt[idx] : 0;
    __syncthreads();
#pragma unroll
    for (int off = 64; off; off >>= 1) {
        if (threadIdx.x < off) sm[threadIdx.x] += sm[threadIdx.x + off];
        __syncthreads();
    }
    if (threadIdx.x == 0) bsum[blockIdx.x] = sm[0];
}
__global__ void scan_bsum(int* __restrict__ bsum, int* __restrict__ rowptr) {
    __shared__ int sm[512];
    int t = threadIdx.x;
    int v = (t < NB) ? bsum[t] : 0;
    sm[t] = v;
    __syncthreads();
#pragma unroll
    for (int off = 1; off < 512; off <<= 1) {
        int x = (t >= off) ? sm[t - off] : 0;
        __syncthreads();
        sm[t] += x;
        __syncthreads();
    }
    if (t < NB) bsum[t] = sm[t] - v;       // exclusive
    if (t == 0) rowptr[NN] = EE;
}
__global__ void write_rowptr(const int* __restrict__ cnt, const int* __restrict__ bsum,
                             int* __restrict__ rowptr, int* __restrict__ cur) {
    __shared__ int sm[128];
    int b = blockIdx.x, t = threadIdx.x;
    int idx = b * 128 + t;
    int v = (idx < NN) ? cnt[idx] : 0;
    sm[t] = v;
    __syncthreads();
#pragma unroll
    for (int off = 1; off < 128; off <<= 1) {
        int x = (t >= off) ? sm[t - off] : 0;
        __syncthreads();
        sm[t] += x;
        __syncthreads();
    }
    if (idx < NN) {
        int r = bsum[b] + sm[t] - v;
        rowptr[idx] = r;
        cur[idx] = r;
    }
}
__global__ void fill_csr(const int* __restrict__ ei, int* __restrict__ cur,
                         int* __restrict__ csrsrc) {
    int i = blockIdx.x * blockDim.x + threadIdx.x;
    if (i >= EE) return;
    int pos = atomicAdd(&cur[ei[EE + i]], 1);
    csrsrc[pos] = ei[i];
}

// ---------------- fused per-node attention (fp16 gathers, fp32 math) --------
// block = dst node, warp = head.
// mode 0 (layer 1): val = skip + msg, ELU -> fp16 A (layer-2 GEMM input)
// mode 1 (layer 2): mean over heads + skip + ELU -> fp32 h2
__global__ __launch_bounds__(128) void att_fused(
    const __half* __restrict__ qkv, int stride, int qOff, int kOff, int vOff,
    const int* __restrict__ rowptr, const int* __restrict__ csrsrc,
    float* __restrict__ alpha,
    int skipOff, int mode,
    __half* __restrict__ Aout, float* __restrict__ h2)
{
    int n = blockIdx.x;
    int h = threadIdx.x >> 5, lane = threadIdx.x & 31;
    int r0 = rowptr[n], r1 = rowptr[n + 1];

    const __half2* qp = reinterpret_cast<const __half2*>(
        qkv + (size_t)n * stride + qOff + h * CC + lane * 4);
    float2 q01 = __half22float2(qp[0]);
    float2 q23 = __half22float2(qp[1]);

    float m = -3.0e38f;
    for (int j = r0; j < r1; j++) {
        int src = csrsrc[j];
        const __half2* kp = reinterpret_cast<const __half2*>(
            qkv + (size_t)src * stride + kOff + h * CC + lane * 4);
        float2 k01 = __half22float2(kp[0]);
        float2 k23 = __half22float2(kp[1]);
        float d = q01.x * k01.x + q01.y * k01.y + q23.x * k23.x + q23.y * k23.y;
#pragma unroll
        for (int o = 16; o; o >>= 1) d += __shfl_xor_sync(0xFFFFFFFFu, d, o);
        d *= 0.08838834764831845f;     // 1/sqrt(128)
        m = fmaxf(m, d);
        if (lane == 0) alpha[(size_t)j * HH + h] = d;
    }
    __syncwarp();

    float s = 0.f;
    float4 acc = make_float4(0.f, 0.f, 0.f, 0.f);
    for (int j = r0; j < r1; j++) {
        int src = csrsrc[j];
        float e = __expf(alpha[(size_t)j * HH + h] - m);
        s += e;
        const __half2* vp = reinterpret_cast<const __half2*>(
            qkv + (size_t)src * stride + vOff + h * CC + lane * 4);
        float2 v01 = __half22float2(vp[0]);
        float2 v23 = __half22float2(vp[1]);
        acc.x += e * v01.x; acc.y += e * v01.y;
        acc.z += e * v23.x; acc.w += e * v23.y;
    }
    float inv = 1.f / (s + EPS);

    if (mode == 0) {
        const __half2* sp = reinterpret_cast<const __half2*>(
            qkv + (size_t)n * stride + skipOff + h * CC + lane * 4);
        float2 s01 = __half22float2(sp[0]);
        float2 s23 = __half22float2(sp[1]);
        float v[4];
        v[0] = s01.x + acc.x * inv; v[1] = s01.y + acc.y * inv;
        v[2] = s23.x + acc.z * inv; v[3] = s23.y + acc.w * inv;
#pragma unroll
        for (int u = 0; u < 4; u++) v[u] = v[u] > 0.f ? v[u] : expm1f(v[u]);  // ELU
        __half2* op = reinterpret_cast<__half2*>(Aout + (size_t)n * KMAX + h * CC + lane * 4);
        op[0] = __floats2half2_rn(v[0], v[1]);
        op[1] = __floats2half2_rn(v[2], v[3]);
    } else {
        __shared__ float sm[HH][CC];
        float qsc = inv * 0.25f;
        sm[h][lane * 4 + 0] = acc.x * qsc;
        sm[h][lane * 4 + 1] = acc.y * qsc;
        sm[h][lane * 4 + 2] = acc.z * qsc;
        sm[h][lane * 4 + 3] = acc.w * qsc;
        __syncthreads();
        int c = threadIdx.x;
        float val = sm[0][c] + sm[1][c] + sm[2][c] + sm[3][c];
        float sk = __half2float(qkv[(size_t)n * stride + skipOff + c]);
        float r = sk + val;
        h2[(size_t)n * CC + c] = r > 0.f ? r : expm1f(r);   // fused ELU
    }
}

// ---------------- pooling + head ----------------
__global__ void zero_pool(float* __restrict__ pool, float* __restrict__ cnt) {
    int i = blockIdx.x * blockDim.x + threadIdx.x;
    if (i < GG * CC) pool[i] = 0.f;
    if (i < GG) cnt[i] = 0.f;
}
__global__ __launch_bounds__(128) void pool_k(
    const float* __restrict__ h, const int* __restrict__ batch,
    float* __restrict__ pool, float* __restrict__ cnt)
{
    int i = blockIdx.x;
    int g = batch[i];
    int c = threadIdx.x;
    atomicAdd(&pool[(size_t)g * CC + c], h[(size_t)i * CC + c]);
    if (c == 0) atomicAdd(&cnt[g], 1.f);
}
__global__ __launch_bounds__(128) void head_k(
    const float* __restrict__ pool, const float* __restrict__ cnt,
    const float* __restrict__ Wfc, const float* __restrict__ bfc,
    float* __restrict__ out)
{
    int g = blockIdx.x, t = threadIdx.x;
    __shared__ float sm[CC];
    __shared__ float logits[NCLS];
    float cv = fmaxf(cnt[g], 1.f);
    sm[t] = pool[(size_t)g * CC + t] / cv;
    __syncthreads();
    if (t < NCLS) {
        float acc = bfc[t];
#pragma unroll 4
        for (int c = 0; c < CC; c++) acc += sm[c] * Wfc[c * NCLS + t];
        logits[t] = acc;
    }
    __syncthreads();
    if (t == 0) {
        float mx = -1e30f;
#pragma unroll
        for (int j = 0; j < NCLS; j++) mx = fmaxf(mx, logits[j]);
        float ssum = 0.f;
#pragma unroll
        for (int j = 0; j < NCLS; j++) ssum += expf(logits[j] - mx);
        float lse = mx + logf(ssum);
#pragma unroll
        for (int j = 0; j < NCLS; j++) out[g * NCLS + j] = logits[j] - lse;
    }
}

// ---------------- launch ----------------
extern "C" void kernel_launch(void* const* d_in, const int* in_sizes, int n_in,
                              void* d_out, int out_size)
{
    const float* x     = (const float*)d_in[0];
    const int*   ei    = (const int*)d_in[1];
    const int*   batch = (const int*)d_in[2];
    const float* Wq1 = (const float*)d_in[3];  const float* bq1 = (const float*)d_in[4];
    const float* Wk1 = (const float*)d_in[5];  const float* bk1 = (const float*)d_in[6];
    const float* Wv1 = (const float*)d_in[7];  const float* bv1 = (const float*)d_in[8];
    const float* Ws1 = (const float*)d_in[9];  const float* bs1 = (const float*)d_in[10];
    const float* Wq2 = (const float*)d_in[11]; const float* bq2 = (const float*)d_in[12];
    const float* Wk2 = (const float*)d_in[13]; const float* bk2 = (const float*)d_in[14];
    const float* Wv2 = (const float*)d_in[15]; const float* bv2 = (const float*)d_in[16];
    const float* Ws2 = (const float*)d_in[17]; const float* bs2 = (const float*)d_in[18];
    const float* Wfc = (const float*)d_in[19]; const float* bfc = (const float*)d_in[20];
    float* out = (float*)d_out;

    __half *qkvs1, *qkvs2, *A, *B;
    float *bias, *alpha, *pool, *cntg, *h2;
    int *cnt, *bsum, *rowptr, *cur, *csrsrc;
    cudaGetSymbolAddress((void**)&qkvs1, g_qkvs1);
    cudaGetSymbolAddress((void**)&qkvs2, g_qkvs2);
    cudaGetSymbolAddress((void**)&A, g_A);
    cudaGetSymbolAddress((void**)&B, g_B);
    cudaGetSymbolAddress((void**)&h2, g_h2);
    cudaGetSymbolAddress((void**)&bias, g_biasv);
    cudaGetSymbolAddress((void**)&alpha, g_alpha);
    cudaGetSymbolAddress((void**)&cnt, g_cnt);
    cudaGetSymbolAddress((void**)&bsum, g_bsum);
    cudaGetSymbolAddress((void**)&rowptr, g_rowptr);
    cudaGetSymbolAddress((void**)&cur, g_cur);
    cudaGetSymbolAddress((void**)&csrsrc, g_csrsrc);
    cudaGetSymbolAddress((void**)&pool, g_pool);
    cudaGetSymbolAddress((void**)&cntg, g_cnt_g);

    cudaFuncSetAttribute(gemm_f16, cudaFuncAttributeMaxDynamicSharedMemorySize, SMEM_GEMM);

    dim3 tb(32, 8);

    // ---------- layer 1 prep, then GEMM ----------
    split_bT<<<dim3(512 / 32, FF / 32), tb>>>(Wq1, bq1, FF, 512, 0,    B, bias);
    split_bT<<<dim3(512 / 32, FF / 32), tb>>>(Wk1, bk1, FF, 512, 512,  B, bias);
    split_bT<<<dim3(512 / 32, FF / 32), tb>>>(Wv1, bv1, FF, 512, 1024, B, bias);
    split_bT<<<dim3(512 / 32, FF / 32), tb>>>(Ws1, bs1, FF, 512, 1536, B, bias);
    cvt_a<<<(int)(((size_t)NN * FF + 255) / 256), 256>>>(x, FF, A);

    gemm_f16<<<dim3(N1 / 128, NB), 256, SMEM_GEMM>>>(
        A, FF, FF, B, bias, qkvs1, N1, NN);

    // ---------- CSR build (once, reused by both layers) ----------
    zero_cnt<<<(NN + 255) / 256, 256>>>(cnt);
    hist_dst<<<(EE + 255) / 256, 256>>>(ei, cnt);
    blocksum<<<NB, 128>>>(cnt, bsum);
    scan_bsum<<<1, 512>>>(bsum, rowptr);
    write_rowptr<<<NB, 128>>>(cnt, bsum, rowptr, cur);
    fill_csr<<<(EE + 255) / 256, 256>>>(ei, cur, csrsrc);

    // ---------- layer 1 attention (emits layer-2 GEMM fp16 input directly) ----------
    att_fused<<<NN, 128>>>(qkvs1, N1, 0, 512, 1024, rowptr, csrsrc, alpha,
                           1536, 0, A, nullptr);

    // ---------- layer 2 prep ----------
    split_bT<<<dim3(512 / 32, 512 / 32), tb>>>(Wq2, bq2, 512, 512, 0,    B, bias);
    split_bT<<<dim3(512 / 32, 512 / 32), tb>>>(Wk2, bk2, 512, 512, 512,  B, bias);
    split_bT<<<dim3(512 / 32, 512 / 32), tb>>>(Wv2, bv2, 512, 512, 1024, B, bias);
    split_bT<<<dim3(128 / 32, 512 / 32), tb>>>(Ws2, bs2, 512, 128, 1536, B, bias);

    // ---------- layer 2 fused GEMM + attention (mean + skip + ELU fused) ----------
    gemm_f16<<<dim3(N2 / 128, NB), 256, SMEM_GEMM>>>(
        A, 512, 512, B, bias, qkvs2, N2, NN);
    att_fused<<<NN, 128>>>(qkvs2, N2, 0, 512, 1024, rowptr, csrsrc, alpha,
                           1536, 1, nullptr, h2);

    // ---------- pooling + classifier ----------
    zero_pool<<<(GG * CC + 255) / 256, 256>>>(pool, cntg);
    pool_k<<<NN, 128>>>(h2, batch, pool, cntg);
    head_k<<<GG, 128>>>(pool, cntg, Wfc, bfc, out);
}

// round 8
// speedup vs baseline: 5.8596x; 1.1884x over previous
#include <cuda_runtime.h>
#include <cuda_fp16.h>
#include <cstdint>
#include <cstddef>

// ---------------- problem dims ----------------
#define NN 50000
#define FF 256
#define EE 200000
#define HH 4
#define CC 128
#define GG 256
#define NCLS 10
#define EPS 1e-16f

#define N1 2048            // layer1 fused output cols: q|k|v|skip (4*512)
#define N2 1664            // layer2 fused output cols: q|k|v (3*512) | skip (128)
#define KMAX 512
#define NB 391             // ceil(NN/128)
#define BROWS (N1 + N2)    // 3712 weight rows total (both layers)

// ---------------- scratch (device globals) ----------------
__device__ __align__(256) __half g_qkvs1[(size_t)NN * N1];
__device__ __align__(256) __half g_qkvs2[(size_t)NN * N2];
__device__ __align__(256) __half g_A[(size_t)NN * KMAX];
__device__ __align__(256) __half g_B[(size_t)BROWS * KMAX];
__device__ __align__(256) float  g_h2[(size_t)NN * CC];
__device__ __align__(256) float  g_biasv[BROWS];
__device__ __align__(256) int    g_cnt[NN];
__device__ __align__(256) int    g_bsum[512];
__device__ __align__(256) int    g_rowptr[NN + 1];
__device__ __align__(256) int    g_cur[NN];
__device__ __align__(256) int    g_csrsrc[EE];

// ---------------- PTX helpers (sm_80-generic) ----------------
__device__ __forceinline__ uint32_t smem_u32(const void* p) {
    uint32_t a;
    asm("{ .reg .u64 t; cvta.to.shared.u64 t, %1; cvt.u32.u64 %0, t; }" : "=r"(a) : "l"(p));
    return a;
}
__device__ __forceinline__ void cp16(uint32_t dst, const void* src, unsigned srcsz) {
    asm volatile("cp.async.cg.shared.global [%0], [%1], 16, %2;"
                 :: "r"(dst), "l"(src), "r"(srcsz) : "memory");
}
__device__ __forceinline__ void ldsm4(uint32_t& r0, uint32_t& r1, uint32_t& r2, uint32_t& r3,
                                      uint32_t a) {
    asm volatile("ldmatrix.sync.aligned.m8n8.x4.shared.b16 {%0,%1,%2,%3}, [%4];"
                 : "=r"(r0), "=r"(r1), "=r"(r2), "=r"(r3) : "r"(a));
}
__device__ __forceinline__ void mma_f16(float* c, const uint32_t* a, const uint32_t* b) {
    asm volatile(
        "mma.sync.aligned.m16n8k16.row.col.f32.f16.f16.f32 "
        "{%0,%1,%2,%3}, {%4,%5,%6,%7}, {%8,%9}, {%0,%1,%2,%3};"
        : "+f"(c[0]), "+f"(c[1]), "+f"(c[2]), "+f"(c[3])
        : "r"(a[0]), "r"(a[1]), "r"(a[2]), "r"(a[3]), "r"(b[0]), "r"(b[1]));
}

// ---------------- fp16 tensor-core GEMM (1 MMA pass, 4-stage cp.async) ------
#define TILE_B   (128 * 80)
#define STAGE_B  (2 * TILE_B)
#define SMEM_GEMM (4 * STAGE_B)           // 81920 B

__global__ __launch_bounds__(256)
void gemm_f16(const __half* __restrict__ Ab, int lda, int K,
              const __half* __restrict__ Bb,
              const float* __restrict__ bias, __half* __restrict__ Cout, int ldo, int nrows)
{
    extern __shared__ char smem[];
    const uint32_t sb = smem_u32(smem);
    const int tid = threadIdx.x;
    const int lane = tid & 31;
    const int wid = tid >> 5;
    const int warpM = wid & 1;
    const int warpN = wid >> 1;
    const int rowBase = blockIdx.y * 128;
    const int colBase = blockIdx.x * 128;

    float acc[4][4][4];
#pragma unroll
    for (int i = 0; i < 4; i++)
#pragma unroll
        for (int j = 0; j < 4; j++)
#pragma unroll
            for (int f = 0; f < 4; f++) acc[i][j][f] = 0.f;

    const int T = K >> 5;

    auto loadStage = [&](int s, int k0) {
        uint32_t base = sb + s * STAGE_B;
#pragma unroll
        for (int t = 0; t < 2; t++) {
            int c = tid + t * 256;
            int r = c >> 2;
            int q = c & 3;
            uint32_t soff = (uint32_t)(r * 80 + q * 16);
            int ga = rowBase + r;
            unsigned va = (ga < nrows) ? 16u : 0u;
            int gac = (ga < nrows) ? ga : (nrows - 1);
            cp16(base + soff,          Ab + (size_t)gac * lda + k0 + q * 8, va);
            cp16(base + TILE_B + soff, Bb + (size_t)(colBase + r) * KMAX + k0 + q * 8, 16u);
        }
        asm volatile("cp.async.commit_group;" ::: "memory");
    };

    const uint32_t aOff = (uint32_t)((warpM * 64 + (lane & 15)) * 80 + (lane >> 4) * 16);
    const uint32_t bOff = (uint32_t)((warpN * 32 + (lane & 7) + ((lane >> 4) & 1) * 8) * 80
                                     + ((lane >> 3) & 1) * 16);

    loadStage(0, 0);
    loadStage(1, 32);

    for (int it = 0; it < T; it++) {
        if (it + 2 < T) loadStage((it + 2) & 3, (it + 2) << 5);
        int pend = ((it + 2 < T) ? 2 : (it + 1 < T) ? 1 : 0);
        if (pend == 2)      asm volatile("cp.async.wait_group 2;" ::: "memory");
        else if (pend == 1) asm volatile("cp.async.wait_group 1;" ::: "memory");
        else                asm volatile("cp.async.wait_group 0;" ::: "memory");
        __syncthreads();

        uint32_t tb = sb + (it & 3) * STAGE_B;
#pragma unroll
        for (int ks = 0; ks < 2; ks++) {
            uint32_t kb = ks * 32;
            uint32_t ah[4][4];
#pragma unroll
            for (int i = 0; i < 4; i++) {
                uint32_t ad = tb + aOff + i * (16 * 80) + kb;
                ldsm4(ah[i][0], ah[i][1], ah[i][2], ah[i][3], ad);
            }
            uint32_t bb[4][2];
#pragma unroll
            for (int j2 = 0; j2 < 2; j2++) {
                uint32_t bd = tb + TILE_B + bOff + j2 * (16 * 80) + kb;
                uint32_t t0, t1, t2, t3;
                ldsm4(t0, t1, t2, t3, bd);
                bb[j2 * 2][0] = t0; bb[j2 * 2][1] = t1;
                bb[j2 * 2 + 1][0] = t2; bb[j2 * 2 + 1][1] = t3;
            }
#pragma unroll
            for (int i = 0; i < 4; i++)
#pragma unroll
                for (int j = 0; j < 4; j++)
                    mma_f16(acc[i][j], ah[i], bb[j]);
        }
    }

#pragma unroll
    for (int i = 0; i < 4; i++) {
        int r0 = rowBase + warpM * 64 + i * 16 + (lane >> 2);
#pragma unroll
        for (int rr = 0; rr < 2; rr++) {
            int grow = r0 + rr * 8;
            if (grow >= nrows) continue;
#pragma unroll
            for (int j = 0; j < 4; j++) {
                int gc = colBase + warpN * 32 + j * 8 + (lane & 3) * 2;
                __half2 o = __floats2half2_rn(acc[i][j][rr * 2 + 0] + bias[gc + 0],
                                              acc[i][j][rr * 2 + 1] + bias[gc + 1]);
                *reinterpret_cast<__half2*>(Cout + (size_t)grow * ldo + gc) = o;
            }
        }
    }
}

// ---------------- mega prep kernel ----------------
// grid (16, 16, 9), block (32, 8).
// z = 0..7: transpose+convert one weight matrix into B[(rowOff+n)*KMAX+k] + bias.
// z = 8:    cvt x -> fp16 A, zero cnt.
__global__ void prep(
    const float* __restrict__ Wq1, const float* __restrict__ bq1,
    const float* __restrict__ Wk1, const float* __restrict__ bk1,
    const float* __restrict__ Wv1, const float* __restrict__ bv1,
    const float* __restrict__ Ws1, const float* __restrict__ bs1,
    const float* __restrict__ Wq2, const float* __restrict__ bq2,
    const float* __restrict__ Wk2, const float* __restrict__ bk2,
    const float* __restrict__ Wv2, const float* __restrict__ bv2,
    const float* __restrict__ Ws2, const float* __restrict__ bs2,
    const float* __restrict__ x,
    __half* __restrict__ B, float* __restrict__ bias,
    __half* __restrict__ A, int* __restrict__ cnt)
{
    int task = blockIdx.z;
    int tx = threadIdx.x, ty = threadIdx.y;

    if (task == 8) {
        int bid = blockIdx.y * 16 + blockIdx.x;         // 0..255
        int tid = ty * 32 + tx;                         // 0..255
        size_t start = (size_t)bid * 256 + tid;
        for (size_t i = start; i < (size_t)NN * FF; i += 65536)
            A[i] = __float2half_rn(x[i]);
        for (size_t i = start; i < NN; i += 65536)
            cnt[i] = 0;
        return;
    }

    const float *W, *b;
    int K, M, rowOff;
    switch (task) {
        case 0: W = Wq1; b = bq1; K = FF;  M = 512; rowOff = 0;    break;
        case 1: W = Wk1; b = bk1; K = FF;  M = 512; rowOff = 512;  break;
        case 2: W = Wv1; b = bv1; K = FF;  M = 512; rowOff = 1024; break;
        case 3: W = Ws1; b = bs1; K = FF;  M = 512; rowOff = 1536; break;
        case 4: W = Wq2; b = bq2; K = 512; M = 512; rowOff = 2048; break;
        case 5: W = Wk2; b = bk2; K = 512; M = 512; rowOff = 2560; break;
        case 6: W = Wv2; b = bv2; K = 512; M = 512; rowOff = 3072; break;
        default: W = Ws2; b = bs2; K = 512; M = 128; rowOff = 3584; break;
    }
    int nb = blockIdx.x * 32, kb = blockIdx.y * 32;
    if (nb >= M || kb >= K) return;

    __shared__ float tile[32][33];
#pragma unroll
    for (int i = 0; i < 4; i++)
        tile[ty + i * 8][tx] = W[(size_t)(kb + ty + i * 8) * M + nb + tx];
    __syncthreads();
#pragma unroll
    for (int i = 0; i < 4; i++)
        B[(size_t)(rowOff + nb + ty + i * 8) * KMAX + kb + tx] =
            __float2half_rn(tile[tx][ty + i * 8]);
    if (ty == 0 && blockIdx.y == 0) bias[rowOff + nb + tx] = b[nb + tx];
}

// ---------------- CSR build ----------------
__global__ void hist_dst(const int* __restrict__ ei, int* __restrict__ cnt) {
    int i = blockIdx.x * blockDim.x + threadIdx.x;
    if (i < EE) atomicAdd(&cnt[ei[EE + i]], 1);
}
__global__ void blocksum(const int* __restrict__ cnt, int* __restrict__ bsum) {
    __shared__ int sm[128];
    int idx = blockIdx.x * 128 + threadIdx.x;
    sm[threadIdx.x] = (idx < NN) ? cnt[idx] : 0;
    __syncthreads();
#pragma unroll
    for (int off = 64; off; off >>= 1) {
        if (threadIdx.x < off) sm[threadIdx.x] += sm[threadIdx.x + off];
        __syncthreads();
    }
    if (threadIdx.x == 0) bsum[blockIdx.x] = sm[0];
}
// per-block: reduce bsum[0..b) for base, then intra-block exclusive scan of cnt.
__global__ void write_rowptr(const int* __restrict__ cnt, const int* __restrict__ bsum,
                             int* __restrict__ rowptr, int* __restrict__ cur) {
    __shared__ int part[128];
    __shared__ int sm[128];
    int b = blockIdx.x, t = threadIdx.x;
    int a = 0;
    for (int i = t; i < b; i += 128) a += bsum[i];
    part[t] = a;
    __syncthreads();
#pragma unroll
    for (int off = 64; off; off >>= 1) {
        if (t < off) part[t] += part[t + off];
        __syncthreads();
    }
    int base = part[0];
    int idx = b * 128 + t;
    int v = (idx < NN) ? cnt[idx] : 0;
    sm[t] = v;
    __syncthreads();
#pragma unroll
    for (int off = 1; off < 128; off <<= 1) {
        int x = (t >= off) ? sm[t - off] : 0;
        __syncthreads();
        sm[t] += x;
        __syncthreads();
    }
    if (idx < NN) {
        int r = base + sm[t] - v;
        rowptr[idx] = r;
        cur[idx] = r;
        if (idx == NN - 1) rowptr[NN] = r + v;
    }
}
__global__ void fill_csr(const int* __restrict__ ei, int* __restrict__ cur,
                         int* __restrict__ csrsrc) {
    int i = blockIdx.x * blockDim.x + threadIdx.x;
    if (i >= EE) return;
    int pos = atomicAdd(&cur[ei[EE + i]], 1);
    csrsrc[pos] = ei[i];
}

// ---------------- fused per-node attention (online softmax, single pass) ----
// block = dst node, warp = head.
// mode 0 (layer 1): val = skip + msg, ELU -> fp16 A (layer-2 GEMM input)
// mode 1 (layer 2): mean over heads + skip + ELU -> fp32 h2
__global__ __launch_bounds__(128) void att_fused(
    const __half* __restrict__ qkv, int stride, int qOff, int kOff, int vOff,
    const int* __restrict__ rowptr, const int* __restrict__ csrsrc,
    int skipOff, int mode,
    __half* __restrict__ Aout, float* __restrict__ h2)
{
    int n = blockIdx.x;
    int h = threadIdx.x >> 5, lane = threadIdx.x & 31;
    int r0 = rowptr[n], r1 = rowptr[n + 1];
    const int hoff = h * CC + lane * 4;

    uint2 qraw = *reinterpret_cast<const uint2*>(qkv + (size_t)n * stride + qOff + hoff);
    float2 q01 = __half22float2(*reinterpret_cast<__half2*>(&qraw.x));
    float2 q23 = __half22float2(*reinterpret_cast<__half2*>(&qraw.y));

    float m = -3.0e38f, s = 0.f;
    float4 acc = make_float4(0.f, 0.f, 0.f, 0.f);
    for (int j = r0; j < r1; j++) {
        int src = csrsrc[j];
        const __half* base = qkv + (size_t)src * stride;
        uint2 kraw = *reinterpret_cast<const uint2*>(base + kOff + hoff);
        uint2 vraw = *reinterpret_cast<const uint2*>(base + vOff + hoff);
        float2 k01 = __half22float2(*reinterpret_cast<__half2*>(&kraw.x));
        float2 k23 = __half22float2(*reinterpret_cast<__half2*>(&kraw.y));
        float d = q01.x * k01.x + q01.y * k01.y + q23.x * k23.x + q23.y * k23.y;
#pragma unroll
        for (int o = 16; o; o >>= 1) d += __shfl_xor_sync(0xFFFFFFFFu, d, o);
        d *= 0.08838834764831845f;          // 1/sqrt(128)
        float mn = fmaxf(m, d);
        float corr = __expf(m - mn);        // first iter: exp(-inf) = 0
        float p = __expf(d - mn);
        float2 v01 = __half22float2(*reinterpret_cast<__half2*>(&vraw.x));
        float2 v23 = __half22float2(*reinterpret_cast<__half2*>(&vraw.y));
        s = s * corr + p;
        acc.x = acc.x * corr + p * v01.x;
        acc.y = acc.y * corr + p * v01.y;
        acc.z = acc.z * corr + p * v23.x;
        acc.w = acc.w * corr + p * v23.y;
        m = mn;
    }
    float inv = 1.f / (s + EPS);

    if (mode == 0) {
        uint2 sraw = *reinterpret_cast<const uint2*>(qkv + (size_t)n * stride + skipOff + hoff);
        float2 s01 = __half22float2(*reinterpret_cast<__half2*>(&sraw.x));
        float2 s23 = __half22float2(*reinterpret_cast<__half2*>(&sraw.y));
        float v[4];
        v[0] = s01.x + acc.x * inv; v[1] = s01.y + acc.y * inv;
        v[2] = s23.x + acc.z * inv; v[3] = s23.y + acc.w * inv;
#pragma unroll
        for (int u = 0; u < 4; u++) v[u] = v[u] > 0.f ? v[u] : expm1f(v[u]);  // ELU
        __half2* op = reinterpret_cast<__half2*>(Aout + (size_t)n * KMAX + hoff);
        op[0] = __floats2half2_rn(v[0], v[1]);
        op[1] = __floats2half2_rn(v[2], v[3]);
    } else {
        __shared__ float sm[HH][CC];
        float qsc = inv * 0.25f;
        sm[h][lane * 4 + 0] = acc.x * qsc;
        sm[h][lane * 4 + 1] = acc.y * qsc;
        sm[h][lane * 4 + 2] = acc.z * qsc;
        sm[h][lane * 4 + 3] = acc.w * qsc;
        __syncthreads();
        int c = threadIdx.x;
        float val = sm[0][c] + sm[1][c] + sm[2][c] + sm[3][c];
        float sk = __half2float(qkv[(size_t)n * stride + skipOff + c]);
        float r = sk + val;
        h2[(size_t)n * CC + c] = r > 0.f ? r : expm1f(r);   // fused ELU
    }
}

// ---------------- fused pooling + classifier head ----------------
// block = graph g; batch is SORTED, so segment bounds via binary search.
__global__ __launch_bounds__(128) void poolhead(
    const float* __restrict__ h2, const int* __restrict__ batch,
    const float* __restrict__ Wfc, const float* __restrict__ bfc,
    float* __restrict__ out)
{
    int g = blockIdx.x, t = threadIdx.x;
    __shared__ int ss[2];
    if (t < 2) {
        int target = g + t;
        int lo = 0, hi = NN;
        while (lo < hi) {
            int mid = (lo + hi) >> 1;
            if (batch[mid] < target) lo = mid + 1; else hi = mid;
        }
        ss[t] = lo;
    }
    __syncthreads();
    int s0 = ss[0], s1 = ss[1];

    float sum0 = 0.f, sum1 = 0.f, sum2 = 0.f, sum3 = 0.f;
    int i = s0;
    for (; i + 3 < s1; i += 4) {
        sum0 += h2[(size_t)(i + 0) * CC + t];
        sum1 += h2[(size_t)(i + 1) * CC + t];
        sum2 += h2[(size_t)(i + 2) * CC + t];
        sum3 += h2[(size_t)(i + 3) * CC + t];
    }
    for (; i < s1; i++) sum0 += h2[(size_t)i * CC + t];
    float sum = (sum0 + sum1) + (sum2 + sum3);
    float cv = fmaxf((float)(s1 - s0), 1.f);

    __shared__ float sm[CC];
    __shared__ float logits[NCLS];
    sm[t] = sum / cv;
    __syncthreads();
    if (t < NCLS) {
        float acc = bfc[t];
#pragma unroll 4
        for (int c = 0; c < CC; c++) acc += sm[c] * Wfc[c * NCLS + t];
        logits[t] = acc;
    }
    __syncthreads();
    if (t == 0) {
        float mx = -1e30f;
#pragma unroll
        for (int j = 0; j < NCLS; j++) mx = fmaxf(mx, logits[j]);
        float ssum = 0.f;
#pragma unroll
        for (int j = 0; j < NCLS; j++) ssum += expf(logits[j] - mx);
        float lse = mx + logf(ssum);
#pragma unroll
        for (int j = 0; j < NCLS; j++) out[g * NCLS + j] = logits[j] - lse;
    }
}

// ---------------- launch ----------------
extern "C" void kernel_launch(void* const* d_in, const int* in_sizes, int n_in,
                              void* d_out, int out_size)
{
    const float* x     = (const float*)d_in[0];
    const int*   ei    = (const int*)d_in[1];
    const int*   batch = (const int*)d_in[2];
    const float* Wq1 = (const float*)d_in[3];  const float* bq1 = (const float*)d_in[4];
    const float* Wk1 = (const float*)d_in[5];  const float* bk1 = (const float*)d_in[6];
    const float* Wv1 = (const float*)d_in[7];  const float* bv1 = (const float*)d_in[8];
    const float* Ws1 = (const float*)d_in[9];  const float* bs1 = (const float*)d_in[10];
    const float* Wq2 = (const float*)d_in[11]; const float* bq2 = (const float*)d_in[12];
    const float* Wk2 = (const float*)d_in[13]; const float* bk2 = (const float*)d_in[14];
    const float* Wv2 = (const float*)d_in[15]; const float* bv2 = (const float*)d_in[16];
    const float* Ws2 = (const float*)d_in[17]; const float* bs2 = (const float*)d_in[18];
    const float* Wfc = (const float*)d_in[19]; const float* bfc = (const float*)d_in[20];
    float* out = (float*)d_out;

    __half *qkvs1, *qkvs2, *A, *B;
    float *bias, *h2;
    int *cnt, *bsum, *rowptr, *cur, *csrsrc;
    cudaGetSymbolAddress((void**)&qkvs1, g_qkvs1);
    cudaGetSymbolAddress((void**)&qkvs2, g_qkvs2);
    cudaGetSymbolAddress((void**)&A, g_A);
    cudaGetSymbolAddress((void**)&B, g_B);
    cudaGetSymbolAddress((void**)&h2, g_h2);
    cudaGetSymbolAddress((void**)&bias, g_biasv);
    cudaGetSymbolAddress((void**)&cnt, g_cnt);
    cudaGetSymbolAddress((void**)&bsum, g_bsum);
    cudaGetSymbolAddress((void**)&rowptr, g_rowptr);
    cudaGetSymbolAddress((void**)&cur, g_cur);
    cudaGetSymbolAddress((void**)&csrsrc, g_csrsrc);

    cudaFuncSetAttribute(gemm_f16, cudaFuncAttributeMaxDynamicSharedMemorySize, SMEM_GEMM);

    // 1) mega prep: all weights (both layers) + A convert + cnt zero
    prep<<<dim3(16, 16, 9), dim3(32, 8)>>>(
        Wq1, bq1, Wk1, bk1, Wv1, bv1, Ws1, bs1,
        Wq2, bq2, Wk2, bk2, Wv2, bv2, Ws2, bs2,
        x, B, bias, A, cnt);

    // 2-5) CSR build
    hist_dst<<<(EE + 255) / 256, 256>>>(ei, cnt);
    blocksum<<<NB, 128>>>(cnt, bsum);
    write_rowptr<<<NB, 128>>>(cnt, bsum, rowptr, cur);
    fill_csr<<<(EE + 255) / 256, 256>>>(ei, cur, csrsrc);

    // 6-7) layer 1: GEMM + attention (emits layer-2 fp16 A directly)
    gemm_f16<<<dim3(N1 / 128, NB), 256, SMEM_GEMM>>>(
        A, FF, FF, B, bias, qkvs1, N1, NN);
    att_fused<<<NN, 128>>>(qkvs1, N1, 0, 512, 1024, rowptr, csrsrc,
                           1536, 0, A, nullptr);

    // 8-9) layer 2: GEMM + attention (mean + skip + ELU fused)
    gemm_f16<<<dim3(N2 / 128, NB), 256, SMEM_GEMM>>>(
        A, 512, 512, B + (size_t)N1 * KMAX, bias + N1, qkvs2, N2, NN);
    att_fused<<<NN, 128>>>(qkvs2, N2, 0, 512, 1024, rowptr, csrsrc,
                           1536, 1, nullptr, h2);

    // 10) fused mean-pool + FC + log_softmax
    poolhead<<<GG, 128>>>(h2, batch, Wfc, bfc, out);
}